// round 1
// baseline (speedup 1.0000x reference)
#include <cuda_runtime.h>
#include <math.h>

#define B_    4
#define S_    2048
#define D_    256
#define H_    8
#define DK_   32
#define DFF_  1024
#define M_    (B_*S_)      // 8192
#define LNEPS 1e-5f

// ---------------- scratch (static device globals — allowed) ----------------
__device__ float g_q [M_*D_];
__device__ float g_k [M_*D_];
__device__ float g_v [M_*D_];
__device__ float g_o [M_*D_];
__device__ float g_x1[M_*D_];
__device__ float g_x2[M_*D_];
__device__ float g_h [M_*DFF_];

// ---------------- warp reduce helpers ----------------
__device__ __forceinline__ float warp_sum(float v) {
#pragma unroll
    for (int s = 16; s; s >>= 1) v += __shfl_xor_sync(0xffffffffu, v, s);
    return v;
}
__device__ __forceinline__ float warp_max(float v) {
#pragma unroll
    for (int s = 16; s; s >>= 1) v = fmaxf(v, __shfl_xor_sync(0xffffffffu, v, s));
    return v;
}

// ============================================================================
// GEMM: C[M,O] = relu(A[M,K] @ W[O,K]^T)  (+ R[M,O] if R != nullptr)
// 64x64 tile, 256 threads, 4x4 per thread, BK=16.
// ============================================================================
__global__ void __launch_bounds__(256) gemm_relu_kernel(
    const float* __restrict__ A, const float* __restrict__ W,
    const float* __restrict__ R, float* __restrict__ C,
    int K, int O)
{
    __shared__ __align__(16) float As[16][68];
    __shared__ __align__(16) float Ws[16][68];

    const int m0 = blockIdx.y * 64;
    const int o0 = blockIdx.x * 64;
    const int tid = threadIdx.x;
    const int tx = tid & 15;        // output col group
    const int ty = tid >> 4;        // output row group
    const int lr = tid >> 2;        // load row 0..63
    const int lk = (tid & 3) << 2;  // load k {0,4,8,12}

    float acc[4][4];
#pragma unroll
    for (int i = 0; i < 4; i++)
#pragma unroll
        for (int j = 0; j < 4; j++) acc[i][j] = 0.f;

    for (int kt = 0; kt < K; kt += 16) {
        __syncthreads();
        float4 av = *(const float4*)&A[(size_t)(m0 + lr) * K + kt + lk];
        float4 wv = *(const float4*)&W[(size_t)(o0 + lr) * K + kt + lk];
        As[lk + 0][lr] = av.x; As[lk + 1][lr] = av.y;
        As[lk + 2][lr] = av.z; As[lk + 3][lr] = av.w;
        Ws[lk + 0][lr] = wv.x; Ws[lk + 1][lr] = wv.y;
        Ws[lk + 2][lr] = wv.z; Ws[lk + 3][lr] = wv.w;
        __syncthreads();
#pragma unroll
        for (int k = 0; k < 16; k++) {
            float4 a = *(const float4*)&As[k][ty * 4];
            float4 w = *(const float4*)&Ws[k][tx * 4];
            float aa[4] = {a.x, a.y, a.z, a.w};
            float ww[4] = {w.x, w.y, w.z, w.w};
#pragma unroll
            for (int i = 0; i < 4; i++)
#pragma unroll
                for (int j = 0; j < 4; j++) acc[i][j] = fmaf(aa[i], ww[j], acc[i][j]);
        }
    }

#pragma unroll
    for (int i = 0; i < 4; i++) {
        const int m = m0 + ty * 4 + i;
        float v0 = fmaxf(acc[i][0], 0.f);
        float v1 = fmaxf(acc[i][1], 0.f);
        float v2 = fmaxf(acc[i][2], 0.f);
        float v3 = fmaxf(acc[i][3], 0.f);
        if (R) {
            float4 rv = *(const float4*)&R[(size_t)m * O + o0 + tx * 4];
            v0 += rv.x; v1 += rv.y; v2 += rv.z; v3 += rv.w;
        }
        float4 outv = make_float4(v0, v1, v2, v3);
        *(float4*)&C[(size_t)m * O + o0 + tx * 4] = outv;
    }
}

// ============================================================================
// Flash attention, fp32. One CTA = 64 query rows of one (b,h).
// 4 warps x 16 rows. K/V tiles of 64 rows in padded smem.
// Each lane owns head-dim column c=lane of its warp's 16 rows.
// Scores: lane owns keys {lane, lane+32}. P staged transposed per-warp in smem.
// ============================================================================
__global__ void __launch_bounds__(128) attn_kernel(
    const float* __restrict__ Q, const float* __restrict__ Kb,
    const float* __restrict__ Vb, float* __restrict__ Ob)
{
    __shared__ __align__(16) float qsT[32][68];     // [c][r]  (transposed q)
    __shared__ __align__(16) float ks[64][33];      // [j][c]
    __shared__ __align__(16) float vs[64][33];      // [j][c]
    __shared__ __align__(16) float ps[4][64][20];   // per-warp  [j][r]

    const int tid  = threadIdx.x;
    const int lane = tid & 31;
    const int warp = tid >> 5;
    const int b = blockIdx.z, h = blockIdx.y;
    const int q0 = blockIdx.x * 64;
    const int rbase = warp * 16;
    const float scale = 0.17677669529663687f;  // 1/sqrt(32)

    // load q tile (transposed, prescaled)
    for (int idx = tid; idx < 64 * 32; idx += 128) {
        int r = idx >> 5, c = idx & 31;
        qsT[c][r] = Q[(size_t)(b * S_ + q0 + r) * D_ + h * DK_ + c] * scale;
    }

    float m_r[16], l_r[16], o_r[16];
#pragma unroll
    for (int r = 0; r < 16; r++) { m_r[r] = -1e30f; l_r[r] = 0.f; o_r[r] = 0.f; }

    for (int t = 0; t < S_; t += 64) {
        __syncthreads();
        for (int idx = tid; idx < 64 * 32; idx += 128) {
            int r = idx >> 5, c = idx & 31;
            size_t gi = (size_t)(b * S_ + t + r) * D_ + h * DK_ + c;
            ks[r][c] = Kb[gi];
            vs[r][c] = Vb[gi];
        }
        __syncthreads();

        // ---- scores: s0 = q . k[lane], s1 = q . k[lane+32] ----
        float s0[16], s1[16];
#pragma unroll
        for (int r = 0; r < 16; r++) { s0[r] = 0.f; s1[r] = 0.f; }
#pragma unroll 8
        for (int c = 0; c < 32; c++) {
            float k0 = ks[lane][c];
            float k1 = ks[lane + 32][c];
#pragma unroll
            for (int r4 = 0; r4 < 4; r4++) {
                float4 qv = *(const float4*)&qsT[c][rbase + r4 * 4];
                s0[r4*4+0] = fmaf(qv.x, k0, s0[r4*4+0]); s1[r4*4+0] = fmaf(qv.x, k1, s1[r4*4+0]);
                s0[r4*4+1] = fmaf(qv.y, k0, s0[r4*4+1]); s1[r4*4+1] = fmaf(qv.y, k1, s1[r4*4+1]);
                s0[r4*4+2] = fmaf(qv.z, k0, s0[r4*4+2]); s1[r4*4+2] = fmaf(qv.z, k1, s1[r4*4+2]);
                s0[r4*4+3] = fmaf(qv.w, k0, s0[r4*4+3]); s1[r4*4+3] = fmaf(qv.w, k1, s1[r4*4+3]);
            }
        }

        // ---- online softmax update; stage P transposed: ps[j][r] ----
#pragma unroll
        for (int r = 0; r < 16; r++) {
            float mt = warp_max(fmaxf(s0[r], s1[r]));
            float mn = fmaxf(m_r[r], mt);
            float p0 = __expf(s0[r] - mn);
            float p1 = __expf(s1[r] - mn);
            float rs = warp_sum(p0 + p1);
            float sc = __expf(m_r[r] - mn);
            l_r[r] = l_r[r] * sc + rs;
            o_r[r] *= sc;
            m_r[r] = mn;
            ps[warp][lane][r]      = p0;
            ps[warp][lane + 32][r] = p1;
        }
        __syncwarp();

        // ---- o[r] += sum_j p[r][j] * v[j][lane] ----
#pragma unroll 8
        for (int j = 0; j < 64; j++) {
            float vj = vs[j][lane];
#pragma unroll
            for (int r4 = 0; r4 < 4; r4++) {
                float4 pv = *(const float4*)&ps[warp][j][r4 * 4];
                o_r[r4*4+0] = fmaf(pv.x, vj, o_r[r4*4+0]);
                o_r[r4*4+1] = fmaf(pv.y, vj, o_r[r4*4+1]);
                o_r[r4*4+2] = fmaf(pv.z, vj, o_r[r4*4+2]);
                o_r[r4*4+3] = fmaf(pv.w, vj, o_r[r4*4+3]);
            }
        }
        __syncwarp();
    }

#pragma unroll
    for (int r = 0; r < 16; r++) {
        Ob[(size_t)(b * S_ + q0 + rbase + r) * D_ + h * DK_ + lane] = o_r[r] / l_r[r];
    }
}

// ============================================================================
// LayerNorm over last dim (256). One CTA per row, 256 threads.
// ============================================================================
__global__ void __launch_bounds__(256) ln_kernel(
    const float* __restrict__ X, const float* __restrict__ g,
    const float* __restrict__ b, float* __restrict__ Y)
{
    __shared__ float red[8];
    const int row = blockIdx.x;
    const int tid = threadIdx.x;
    const int lane = tid & 31, warp = tid >> 5;

    float v = X[(size_t)row * D_ + tid];
    float s = warp_sum(v);
    if (!lane) red[warp] = s;
    __syncthreads();
    if (tid < 32) {
        float t = (tid < 8) ? red[tid] : 0.f;
        t = warp_sum(t);
        if (!tid) red[0] = t;
    }
    __syncthreads();
    float mu = red[0] * (1.f / D_);
    float d = v - mu;
    float s2 = warp_sum(d * d);
    __syncthreads();
    if (!lane) red[warp] = s2;
    __syncthreads();
    if (tid < 32) {
        float t = (tid < 8) ? red[tid] : 0.f;
        t = warp_sum(t);
        if (!tid) red[0] = t;
    }
    __syncthreads();
    float var = red[0] * (1.f / D_);
    Y[(size_t)row * D_ + tid] = d * rsqrtf(var + LNEPS) * g[tid] + b[tid];
}

// ============================================================================
// host
// ============================================================================
static void run_gemm(const float* A, const float* W, const float* R, float* C,
                     int K, int O)
{
    dim3 grid(O / 64, M_ / 64);
    gemm_relu_kernel<<<grid, 256>>>(A, W, R, C, K, O);
}

extern "C" void kernel_launch(void* const* d_in, const int* in_sizes, int n_in,
                              void* d_out, int out_size)
{
    const float* x    = (const float*)d_in[0];
    const float* W11  = (const float*)d_in[1];
    const float* W12  = (const float*)d_in[2];
    const float* W13  = (const float*)d_in[3];
    const float* W14  = (const float*)d_in[4];
    const float* W21  = (const float*)d_in[5];
    const float* W22  = (const float*)d_in[6];
    const float* W23  = (const float*)d_in[7];
    const float* W24  = (const float*)d_in[8];
    const float* Wf11 = (const float*)d_in[9];
    const float* Wf21 = (const float*)d_in[10];
    const float* Wf12 = (const float*)d_in[11];
    const float* Wf22 = (const float*)d_in[12];
    const float* g1   = (const float*)d_in[13];
    const float* b1   = (const float*)d_in[14];
    const float* g2   = (const float*)d_in[15];
    const float* b2   = (const float*)d_in[16];
    const float* g3   = (const float*)d_in[17];
    const float* b3   = (const float*)d_in[18];
    const float* g4   = (const float*)d_in[19];
    const float* b4   = (const float*)d_in[20];
    float* out = (float*)d_out;

    float *q, *k, *v, *o, *x1, *x2, *hbuf;
    cudaGetSymbolAddress((void**)&q,    g_q);
    cudaGetSymbolAddress((void**)&k,    g_k);
    cudaGetSymbolAddress((void**)&v,    g_v);
    cudaGetSymbolAddress((void**)&o,    g_o);
    cudaGetSymbolAddress((void**)&x1,   g_x1);
    cudaGetSymbolAddress((void**)&x2,   g_x2);
    cudaGetSymbolAddress((void**)&hbuf, g_h);

    dim3 agrid(S_ / 64, H_, B_);

    // ---------------- block 1 ----------------
    run_gemm(x, W11, nullptr, q, D_, D_);
    run_gemm(x, W12, nullptr, k, D_, D_);
    run_gemm(x, W13, nullptr, v, D_, D_);
    attn_kernel<<<agrid, 128>>>(q, k, v, o);
    run_gemm(o, W14, x, x1, D_, D_);
    ln_kernel<<<M_, 256>>>(x1, g1, b1, x2);
    run_gemm(x2, Wf11, nullptr, hbuf, D_, DFF_);
    run_gemm(hbuf, Wf21, x2, x1, DFF_, D_);
    ln_kernel<<<M_, 256>>>(x1, g2, b2, x2);

    // ---------------- block 2 ----------------
    run_gemm(x2, W21, nullptr, q, D_, D_);
    run_gemm(x2, W22, nullptr, k, D_, D_);
    run_gemm(x2, W23, nullptr, v, D_, D_);
    attn_kernel<<<agrid, 128>>>(q, k, v, o);
    run_gemm(o, W24, x2, x1, D_, D_);
    ln_kernel<<<M_, 256>>>(x1, g3, b3, x2);
    run_gemm(x2, Wf12, nullptr, hbuf, D_, DFF_);
    run_gemm(hbuf, Wf22, x2, x1, DFF_, D_);
    ln_kernel<<<M_, 256>>>(x1, g4, b4, out);
}

// round 3
// speedup vs baseline: 1.3325x; 1.3325x over previous
#include <cuda_runtime.h>
#include <math.h>

#define B_    4
#define S_    2048
#define D_    256
#define H_    8
#define DK_   32
#define DFF_  1024
#define M_    (B_*S_)      // 8192
#define LNEPS 1e-5f

// ---------------- scratch (static device globals — allowed) ----------------
__device__ float g_q [M_*D_];
__device__ float g_k [M_*D_];
__device__ float g_v [M_*D_];
__device__ float g_o [M_*D_];
__device__ float g_x1[M_*D_];
__device__ float g_x2[M_*D_];
__device__ float g_h [M_*DFF_];

// ---------------- warp reduce helpers ----------------
__device__ __forceinline__ float warp_sum(float v) {
#pragma unroll
    for (int s = 16; s; s >>= 1) v += __shfl_xor_sync(0xffffffffu, v, s);
    return v;
}
__device__ __forceinline__ float warp_max(float v) {
#pragma unroll
    for (int s = 16; s; s >>= 1) v = fmaxf(v, __shfl_xor_sync(0xffffffffu, v, s));
    return v;
}

// ---------------- PTX helpers (valid on baseline sm_100 / compute_100) -----
__device__ __forceinline__ unsigned smem_u32(const void* p) {
    unsigned a;
    asm("{ .reg .u64 t; cvta.to.shared.u64 t, %1; cvt.u32.u64 %0, t; }"
        : "=r"(a) : "l"(p));
    return a;
}
__device__ __forceinline__ void cp16(unsigned dst, const void* src) {
    asm volatile("cp.async.cg.shared.global [%0], [%1], 16;" :: "r"(dst), "l"(src));
}
__device__ __forceinline__ unsigned f2tf32(float f) {
    unsigned r;
    asm("cvt.rna.tf32.f32 %0, %1;" : "=r"(r) : "f"(f));
    return r;
}
__device__ __forceinline__ void mma_tf32(float& c0, float& c1, float& c2, float& c3,
                                         unsigned a0, unsigned a1, unsigned a2, unsigned a3,
                                         unsigned b0, unsigned b1) {
    asm volatile(
        "mma.sync.aligned.m16n8k8.row.col.f32.tf32.tf32.f32 "
        "{%0,%1,%2,%3}, {%4,%5,%6,%7}, {%8,%9}, {%0,%1,%2,%3};"
        : "+f"(c0), "+f"(c1), "+f"(c2), "+f"(c3)
        : "r"(a0), "r"(a1), "r"(a2), "r"(a3), "r"(b0), "r"(b1));
}

// ============================================================================
// tf32 mma.sync GEMM: C[M,O] = relu(A[M,K] @ W[O,K]^T) (+ R if non-null)
// BM=BN=128, BK=16. 256 threads = 8 warps (2m x 4n), warp tile 64x32.
// SMEM rows padded to 20 floats -> conflict-free fragment LDS + aligned cp.async.
// ============================================================================
#define GST 20   // smem row stride in floats (16 data + 4 pad)

__global__ void __launch_bounds__(256) gemm_mma_kernel(
    const float* __restrict__ A, const float* __restrict__ W,
    const float* __restrict__ R, float* __restrict__ C,
    int K, int O)
{
    __shared__ __align__(16) float As[2][128][GST];
    __shared__ __align__(16) float Bs[2][128][GST];

    const int tid  = threadIdx.x;
    const int wid  = tid >> 5;
    const int lane = tid & 31;
    const int g    = lane >> 2;       // groupID (row within fragment)
    const int t    = lane & 3;        // thread-in-group (k within fragment)
    const int m0 = blockIdx.y * 128;
    const int o0 = blockIdx.x * 128;
    const int wm = (wid & 1) * 64;    // warp m offset in tile
    const int wn = (wid >> 1) * 32;   // warp n offset in tile

    const unsigned sa_base = smem_u32(&As[0][0][0]);
    const unsigned sb_base = smem_u32(&Bs[0][0][0]);
    const unsigned stage_bytes = 128u * GST * 4u;

    // load indices: 512 float4 per matrix per stage, 2 per thread
    const int lrow0 = tid >> 1;                 // rows 0..127 (two kq each)
    const int lkq0  = (tid & 1) * 2;            // kq 0/2 then +1

    float acc[4][4][4];
#pragma unroll
    for (int mi = 0; mi < 4; mi++)
#pragma unroll
        for (int ni = 0; ni < 4; ni++)
#pragma unroll
            for (int r = 0; r < 4; r++) acc[mi][ni][r] = 0.f;

    const int nk = K >> 4;

    // ---- prologue: load stage 0 ----
#pragma unroll
    for (int i = 0; i < 2; i++) {
        int kq = lkq0 + i;
        unsigned doff = (unsigned)(lrow0 * (GST * 4) + kq * 16);
        cp16(sa_base + doff, A + (size_t)(m0 + lrow0) * K + kq * 4);
        cp16(sb_base + doff, W + (size_t)(o0 + lrow0) * K + kq * 4);
    }
    asm volatile("cp.async.commit_group;" ::: "memory");

    for (int ki = 0; ki < nk; ki++) {
        const int s = ki & 1;

        if (ki + 1 < nk) {
            const int sn = (ki + 1) & 1;
            const int kt = (ki + 1) << 4;
#pragma unroll
            for (int i = 0; i < 2; i++) {
                int kq = lkq0 + i;
                unsigned doff = (unsigned)(sn * stage_bytes + lrow0 * (GST * 4) + kq * 16);
                cp16(sa_base + doff, A + (size_t)(m0 + lrow0) * K + kt + kq * 4);
                cp16(sb_base + doff, W + (size_t)(o0 + lrow0) * K + kt + kq * 4);
            }
            asm volatile("cp.async.commit_group;" ::: "memory");
            asm volatile("cp.async.wait_group 1;" ::: "memory");
        } else {
            asm volatile("cp.async.wait_group 0;" ::: "memory");
        }
        __syncthreads();

#pragma unroll
        for (int ks = 0; ks < 2; ks++) {
            const int k0 = ks * 8;
            unsigned af[4][4], bf[4][2];
#pragma unroll
            for (int mi = 0; mi < 4; mi++) {
                const int r = wm + mi * 16 + g;
                af[mi][0] = f2tf32(As[s][r    ][k0 + t]);
                af[mi][1] = f2tf32(As[s][r + 8][k0 + t]);
                af[mi][2] = f2tf32(As[s][r    ][k0 + t + 4]);
                af[mi][3] = f2tf32(As[s][r + 8][k0 + t + 4]);
            }
#pragma unroll
            for (int ni = 0; ni < 4; ni++) {
                const int r = wn + ni * 8 + g;
                bf[ni][0] = f2tf32(Bs[s][r][k0 + t]);
                bf[ni][1] = f2tf32(Bs[s][r][k0 + t + 4]);
            }
#pragma unroll
            for (int mi = 0; mi < 4; mi++)
#pragma unroll
                for (int ni = 0; ni < 4; ni++)
                    mma_tf32(acc[mi][ni][0], acc[mi][ni][1], acc[mi][ni][2], acc[mi][ni][3],
                             af[mi][0], af[mi][1], af[mi][2], af[mi][3],
                             bf[ni][0], bf[ni][1]);
        }
        __syncthreads();
    }

    // ---- epilogue: relu (+R) -> C ----
#pragma unroll
    for (int mi = 0; mi < 4; mi++) {
        const int r0 = m0 + wm + mi * 16 + g;
        const int r1 = r0 + 8;
#pragma unroll
        for (int ni = 0; ni < 4; ni++) {
            const int cb = o0 + wn + ni * 8 + 2 * t;
            float v0 = fmaxf(acc[mi][ni][0], 0.f);
            float v1 = fmaxf(acc[mi][ni][1], 0.f);
            float v2 = fmaxf(acc[mi][ni][2], 0.f);
            float v3 = fmaxf(acc[mi][ni][3], 0.f);
            if (R) {
                float2 ra = *(const float2*)&R[(size_t)r0 * O + cb];
                float2 rb = *(const float2*)&R[(size_t)r1 * O + cb];
                v0 += ra.x; v1 += ra.y; v2 += rb.x; v3 += rb.y;
            }
            *(float2*)&C[(size_t)r0 * O + cb] = make_float2(v0, v1);
            *(float2*)&C[(size_t)r1 * O + cb] = make_float2(v2, v3);
        }
    }
}

// ============================================================================
// Flash attention, fp32 (unchanged — next round's target).
// ============================================================================
__global__ void __launch_bounds__(128) attn_kernel(
    const float* __restrict__ Q, const float* __restrict__ Kb,
    const float* __restrict__ Vb, float* __restrict__ Ob)
{
    __shared__ __align__(16) float qsT[32][68];
    __shared__ __align__(16) float ks[64][33];
    __shared__ __align__(16) float vs[64][33];
    __shared__ __align__(16) float ps[4][64][20];

    const int tid  = threadIdx.x;
    const int lane = tid & 31;
    const int warp = tid >> 5;
    const int b = blockIdx.z, h = blockIdx.y;
    const int q0 = blockIdx.x * 64;
    const int rbase = warp * 16;
    const float scale = 0.17677669529663687f;

    for (int idx = tid; idx < 64 * 32; idx += 128) {
        int r = idx >> 5, c = idx & 31;
        qsT[c][r] = Q[(size_t)(b * S_ + q0 + r) * D_ + h * DK_ + c] * scale;
    }

    float m_r[16], l_r[16], o_r[16];
#pragma unroll
    for (int r = 0; r < 16; r++) { m_r[r] = -1e30f; l_r[r] = 0.f; o_r[r] = 0.f; }

    for (int tt = 0; tt < S_; tt += 64) {
        __syncthreads();
        for (int idx = tid; idx < 64 * 32; idx += 128) {
            int r = idx >> 5, c = idx & 31;
            size_t gi = (size_t)(b * S_ + tt + r) * D_ + h * DK_ + c;
            ks[r][c] = Kb[gi];
            vs[r][c] = Vb[gi];
        }
        __syncthreads();

        float s0[16], s1[16];
#pragma unroll
        for (int r = 0; r < 16; r++) { s0[r] = 0.f; s1[r] = 0.f; }
#pragma unroll 8
        for (int c = 0; c < 32; c++) {
            float k0 = ks[lane][c];
            float k1 = ks[lane + 32][c];
#pragma unroll
            for (int r4 = 0; r4 < 4; r4++) {
                float4 qv = *(const float4*)&qsT[c][rbase + r4 * 4];
                s0[r4*4+0] = fmaf(qv.x, k0, s0[r4*4+0]); s1[r4*4+0] = fmaf(qv.x, k1, s1[r4*4+0]);
                s0[r4*4+1] = fmaf(qv.y, k0, s0[r4*4+1]); s1[r4*4+1] = fmaf(qv.y, k1, s1[r4*4+1]);
                s0[r4*4+2] = fmaf(qv.z, k0, s0[r4*4+2]); s1[r4*4+2] = fmaf(qv.z, k1, s1[r4*4+2]);
                s0[r4*4+3] = fmaf(qv.w, k0, s0[r4*4+3]); s1[r4*4+3] = fmaf(qv.w, k1, s1[r4*4+3]);
            }
        }

#pragma unroll
        for (int r = 0; r < 16; r++) {
            float mt = warp_max(fmaxf(s0[r], s1[r]));
            float mn = fmaxf(m_r[r], mt);
            float p0 = __expf(s0[r] - mn);
            float p1 = __expf(s1[r] - mn);
            float rs = warp_sum(p0 + p1);
            float sc = __expf(m_r[r] - mn);
            l_r[r] = l_r[r] * sc + rs;
            o_r[r] *= sc;
            m_r[r] = mn;
            ps[warp][lane][r]      = p0;
            ps[warp][lane + 32][r] = p1;
        }
        __syncwarp();

#pragma unroll 8
        for (int j = 0; j < 64; j++) {
            float vj = vs[j][lane];
#pragma unroll
            for (int r4 = 0; r4 < 4; r4++) {
                float4 pv = *(const float4*)&ps[warp][j][r4 * 4];
                o_r[r4*4+0] = fmaf(pv.x, vj, o_r[r4*4+0]);
                o_r[r4*4+1] = fmaf(pv.y, vj, o_r[r4*4+1]);
                o_r[r4*4+2] = fmaf(pv.z, vj, o_r[r4*4+2]);
                o_r[r4*4+3] = fmaf(pv.w, vj, o_r[r4*4+3]);
            }
        }
        __syncwarp();
    }

#pragma unroll
    for (int r = 0; r < 16; r++) {
        Ob[(size_t)(b * S_ + q0 + rbase + r) * D_ + h * DK_ + lane] = o_r[r] / l_r[r];
    }
}

// ============================================================================
// LayerNorm over last dim (256). One CTA per row, 256 threads.
// ============================================================================
__global__ void __launch_bounds__(256) ln_kernel(
    const float* __restrict__ X, const float* __restrict__ g,
    const float* __restrict__ b, float* __restrict__ Y)
{
    __shared__ float red[8];
    const int row = blockIdx.x;
    const int tid = threadIdx.x;
    const int lane = tid & 31, warp = tid >> 5;

    float v = X[(size_t)row * D_ + tid];
    float s = warp_sum(v);
    if (!lane) red[warp] = s;
    __syncthreads();
    if (tid < 32) {
        float t = (tid < 8) ? red[tid] : 0.f;
        t = warp_sum(t);
        if (!tid) red[0] = t;
    }
    __syncthreads();
    float mu = red[0] * (1.f / D_);
    float d = v - mu;
    float s2 = warp_sum(d * d);
    __syncthreads();
    if (!lane) red[warp] = s2;
    __syncthreads();
    if (tid < 32) {
        float t = (tid < 8) ? red[tid] : 0.f;
        t = warp_sum(t);
        if (!tid) red[0] = t;
    }
    __syncthreads();
    float var = red[0] * (1.f / D_);
    Y[(size_t)row * D_ + tid] = d * rsqrtf(var + LNEPS) * g[tid] + b[tid];
}

// ============================================================================
// host
// ============================================================================
static void run_gemm(const float* A, const float* W, const float* R, float* C,
                     int K, int O)
{
    dim3 grid(O / 128, M_ / 128);
    gemm_mma_kernel<<<grid, 256>>>(A, W, R, C, K, O);
}

extern "C" void kernel_launch(void* const* d_in, const int* in_sizes, int n_in,
                              void* d_out, int out_size)
{
    const float* x    = (const float*)d_in[0];
    const float* W11  = (const float*)d_in[1];
    const float* W12  = (const float*)d_in[2];
    const float* W13  = (const float*)d_in[3];
    const float* W14  = (const float*)d_in[4];
    const float* W21  = (const float*)d_in[5];
    const float* W22  = (const float*)d_in[6];
    const float* W23  = (const float*)d_in[7];
    const float* W24  = (const float*)d_in[8];
    const float* Wf11 = (const float*)d_in[9];
    const float* Wf21 = (const float*)d_in[10];
    const float* Wf12 = (const float*)d_in[11];
    const float* Wf22 = (const float*)d_in[12];
    const float* g1   = (const float*)d_in[13];
    const float* b1   = (const float*)d_in[14];
    const float* g2   = (const float*)d_in[15];
    const float* b2   = (const float*)d_in[16];
    const float* g3   = (const float*)d_in[17];
    const float* b3   = (const float*)d_in[18];
    const float* g4   = (const float*)d_in[19];
    const float* b4   = (const float*)d_in[20];
    float* out = (float*)d_out;

    float *q, *k, *v, *o, *x1, *x2, *hbuf;
    cudaGetSymbolAddress((void**)&q,    g_q);
    cudaGetSymbolAddress((void**)&k,    g_k);
    cudaGetSymbolAddress((void**)&v,    g_v);
    cudaGetSymbolAddress((void**)&o,    g_o);
    cudaGetSymbolAddress((void**)&x1,   g_x1);
    cudaGetSymbolAddress((void**)&x2,   g_x2);
    cudaGetSymbolAddress((void**)&hbuf, g_h);

    dim3 agrid(S_ / 64, H_, B_);

    // ---------------- block 1 ----------------
    run_gemm(x, W11, nullptr, q, D_, D_);
    run_gemm(x, W12, nullptr, k, D_, D_);
    run_gemm(x, W13, nullptr, v, D_, D_);
    attn_kernel<<<agrid, 128>>>(q, k, v, o);
    run_gemm(o, W14, x, x1, D_, D_);
    ln_kernel<<<M_, 256>>>(x1, g1, b1, x2);
    run_gemm(x2, Wf11, nullptr, hbuf, D_, DFF_);
    run_gemm(hbuf, Wf21, x2, x1, DFF_, D_);
    ln_kernel<<<M_, 256>>>(x1, g2, b2, x2);

    // ---------------- block 2 ----------------
    run_gemm(x2, W21, nullptr, q, D_, D_);
    run_gemm(x2, W22, nullptr, k, D_, D_);
    run_gemm(x2, W23, nullptr, v, D_, D_);
    attn_kernel<<<agrid, 128>>>(q, k, v, o);
    run_gemm(o, W24, x2, x1, D_, D_);
    ln_kernel<<<M_, 256>>>(x1, g3, b3, x2);
    run_gemm(x2, Wf12, nullptr, hbuf, D_, DFF_);
    run_gemm(hbuf, Wf22, x2, x1, DFF_, D_);
    ln_kernel<<<M_, 256>>>(x1, g4, b4, out);
}

// round 4
// speedup vs baseline: 2.6557x; 1.9931x over previous
#include <cuda_runtime.h>
#include <math.h>

#define B_    4
#define S_    2048
#define D_    256
#define H_    8
#define DK_   32
#define DFF_  1024
#define M_    (B_*S_)      // 8192
#define LNEPS 1e-5f

// ---------------- scratch (static device globals — allowed) ----------------
__device__ float g_q [M_*D_];
__device__ float g_k [M_*D_];
__device__ float g_v [M_*D_];
__device__ float g_o [M_*D_];
__device__ float g_x1[M_*D_];
__device__ float g_x2[M_*D_];
__device__ float g_h [M_*DFF_];

// ---------------- warp reduce helpers ----------------
__device__ __forceinline__ float warp_sum(float v) {
#pragma unroll
    for (int s = 16; s; s >>= 1) v += __shfl_xor_sync(0xffffffffu, v, s);
    return v;
}

// ---------------- PTX helpers (baseline sm_100-safe) ----------------
__device__ __forceinline__ unsigned smem_u32(const void* p) {
    unsigned a;
    asm("{ .reg .u64 t; cvta.to.shared.u64 t, %1; cvt.u32.u64 %0, t; }"
        : "=r"(a) : "l"(p));
    return a;
}
__device__ __forceinline__ void cp16(unsigned dst, const void* src) {
    asm volatile("cp.async.cg.shared.global [%0], [%1], 16;" :: "r"(dst), "l"(src));
}
__device__ __forceinline__ unsigned f2tf32(float f) {
    unsigned r;
    asm("cvt.rna.tf32.f32 %0, %1;" : "=r"(r) : "f"(f));
    return r;
}
__device__ __forceinline__ void mma_tf32(float& c0, float& c1, float& c2, float& c3,
                                         unsigned a0, unsigned a1, unsigned a2, unsigned a3,
                                         unsigned b0, unsigned b1) {
    asm volatile(
        "mma.sync.aligned.m16n8k8.row.col.f32.tf32.tf32.f32 "
        "{%0,%1,%2,%3}, {%4,%5,%6,%7}, {%8,%9}, {%0,%1,%2,%3};"
        : "+f"(c0), "+f"(c1), "+f"(c2), "+f"(c3)
        : "r"(a0), "r"(a1), "r"(a2), "r"(a3), "r"(b0), "r"(b1));
}

// ============================================================================
// tf32 mma.sync GEMM: C[M,O] = relu(A[M,K] @ W[O,K]^T) (+ R if non-null)
// BM=BN=128, BK=16. 256 threads = 8 warps (2m x 4n), warp tile 64x32.
// rnd != 0: round outputs to tf32 (rna) so consumers can feed mma without cvt.
// ============================================================================
#define GST 20   // smem row stride in floats (16 data + 4 pad)

__global__ void __launch_bounds__(256) gemm_mma_kernel(
    const float* __restrict__ A, const float* __restrict__ W,
    const float* __restrict__ R, float* __restrict__ C,
    int K, int O, int rnd)
{
    __shared__ __align__(16) float As[2][128][GST];
    __shared__ __align__(16) float Bs[2][128][GST];

    const int tid  = threadIdx.x;
    const int wid  = tid >> 5;
    const int lane = tid & 31;
    const int g    = lane >> 2;
    const int t    = lane & 3;
    const int m0 = blockIdx.y * 128;
    const int o0 = blockIdx.x * 128;
    const int wm = (wid & 1) * 64;
    const int wn = (wid >> 1) * 32;

    const unsigned sa_base = smem_u32(&As[0][0][0]);
    const unsigned sb_base = smem_u32(&Bs[0][0][0]);
    const unsigned stage_bytes = 128u * GST * 4u;

    const int lrow0 = tid >> 1;
    const int lkq0  = (tid & 1) * 2;

    float acc[4][4][4];
#pragma unroll
    for (int mi = 0; mi < 4; mi++)
#pragma unroll
        for (int ni = 0; ni < 4; ni++)
#pragma unroll
            for (int r = 0; r < 4; r++) acc[mi][ni][r] = 0.f;

    const int nk = K >> 4;

#pragma unroll
    for (int i = 0; i < 2; i++) {
        int kq = lkq0 + i;
        unsigned doff = (unsigned)(lrow0 * (GST * 4) + kq * 16);
        cp16(sa_base + doff, A + (size_t)(m0 + lrow0) * K + kq * 4);
        cp16(sb_base + doff, W + (size_t)(o0 + lrow0) * K + kq * 4);
    }
    asm volatile("cp.async.commit_group;" ::: "memory");

    for (int ki = 0; ki < nk; ki++) {
        const int s = ki & 1;

        if (ki + 1 < nk) {
            const int sn = (ki + 1) & 1;
            const int kt = (ki + 1) << 4;
#pragma unroll
            for (int i = 0; i < 2; i++) {
                int kq = lkq0 + i;
                unsigned doff = (unsigned)(sn * stage_bytes + lrow0 * (GST * 4) + kq * 16);
                cp16(sa_base + doff, A + (size_t)(m0 + lrow0) * K + kt + kq * 4);
                cp16(sb_base + doff, W + (size_t)(o0 + lrow0) * K + kt + kq * 4);
            }
            asm volatile("cp.async.commit_group;" ::: "memory");
            asm volatile("cp.async.wait_group 1;" ::: "memory");
        } else {
            asm volatile("cp.async.wait_group 0;" ::: "memory");
        }
        __syncthreads();

#pragma unroll
        for (int ks = 0; ks < 2; ks++) {
            const int k0 = ks * 8;
            unsigned af[4][4], bf[4][2];
#pragma unroll
            for (int mi = 0; mi < 4; mi++) {
                const int r = wm + mi * 16 + g;
                af[mi][0] = f2tf32(As[s][r    ][k0 + t]);
                af[mi][1] = f2tf32(As[s][r + 8][k0 + t]);
                af[mi][2] = f2tf32(As[s][r    ][k0 + t + 4]);
                af[mi][3] = f2tf32(As[s][r + 8][k0 + t + 4]);
            }
#pragma unroll
            for (int ni = 0; ni < 4; ni++) {
                const int r = wn + ni * 8 + g;
                bf[ni][0] = f2tf32(Bs[s][r][k0 + t]);
                bf[ni][1] = f2tf32(Bs[s][r][k0 + t + 4]);
            }
#pragma unroll
            for (int mi = 0; mi < 4; mi++)
#pragma unroll
                for (int ni = 0; ni < 4; ni++)
                    mma_tf32(acc[mi][ni][0], acc[mi][ni][1], acc[mi][ni][2], acc[mi][ni][3],
                             af[mi][0], af[mi][1], af[mi][2], af[mi][3],
                             bf[ni][0], bf[ni][1]);
        }
        __syncthreads();
    }

#pragma unroll
    for (int mi = 0; mi < 4; mi++) {
        const int r0 = m0 + wm + mi * 16 + g;
        const int r1 = r0 + 8;
#pragma unroll
        for (int ni = 0; ni < 4; ni++) {
            const int cb = o0 + wn + ni * 8 + 2 * t;
            float v0 = fmaxf(acc[mi][ni][0], 0.f);
            float v1 = fmaxf(acc[mi][ni][1], 0.f);
            float v2 = fmaxf(acc[mi][ni][2], 0.f);
            float v3 = fmaxf(acc[mi][ni][3], 0.f);
            if (R) {
                float2 ra = *(const float2*)&R[(size_t)r0 * O + cb];
                float2 rb = *(const float2*)&R[(size_t)r1 * O + cb];
                v0 += ra.x; v1 += ra.y; v2 += rb.x; v3 += rb.y;
            }
            if (rnd) {
                v0 = __uint_as_float(f2tf32(v0));
                v1 = __uint_as_float(f2tf32(v1));
                v2 = __uint_as_float(f2tf32(v2));
                v3 = __uint_as_float(f2tf32(v3));
            }
            *(float2*)&C[(size_t)r0 * O + cb] = make_float2(v0, v1);
            *(float2*)&C[(size_t)r1 * O + cb] = make_float2(v2, v3);
        }
    }
}

// ============================================================================
// Flash attention with tf32 mma.sync.
// CTA = 128 thr (4 warps), 64 q rows, KV tiles of 64, double-buffered cp.async.
// Q/K/V are pre-rounded to tf32 by the producing GEMM (rnd=1).
// ============================================================================
#define AKST 36   // K smem row stride (floats)
#define AVST 40   // V smem row stride
#define APST 76   // P smem row stride
#define ATT_SMEM (2*64*AKST*4 + 2*64*AVST*4 + 64*APST*4)   // 58368 B

__global__ void __launch_bounds__(128) attn_mma_kernel(
    const float* __restrict__ Q, const float* __restrict__ Kb,
    const float* __restrict__ Vb, float* __restrict__ Ob)
{
    extern __shared__ __align__(16) float dsm[];
    float* ks_ = dsm;                               // [2][64][AKST]
    float* vs_ = dsm + 2 * 64 * AKST;               // [2][64][AVST]
    float* ps_ = dsm + 2 * 64 * AKST + 2 * 64 * AVST; // [64][APST]

    const int tid  = threadIdx.x;
    const int lane = tid & 31;
    const int warp = tid >> 5;
    const int g = lane >> 2;
    const int t = lane & 3;
    const int b = blockIdx.z, h = blockIdx.y;
    const int q0 = blockIdx.x * 64;
    const int r0 = warp * 16;
    const float scale = 0.17677669529663687f;   // 1/sqrt(32)

    // ---- stage Q (scaled) into ps area, build register fragments ----
    for (int idx = tid; idx < 64 * 32; idx += 128) {
        int r = idx >> 5, c = idx & 31;
        ps_[r * APST + c] = Q[(size_t)(b * S_ + q0 + r) * D_ + h * DK_ + c] * scale;
    }
    __syncthreads();
    unsigned qf[4][4];
#pragma unroll
    for (int kt = 0; kt < 4; kt++) {
        qf[kt][0] = f2tf32(ps_[(r0 + g    ) * APST + kt * 8 + t    ]);
        qf[kt][1] = f2tf32(ps_[(r0 + g + 8) * APST + kt * 8 + t    ]);
        qf[kt][2] = f2tf32(ps_[(r0 + g    ) * APST + kt * 8 + t + 4]);
        qf[kt][3] = f2tf32(ps_[(r0 + g + 8) * APST + kt * 8 + t + 4]);
    }
    __syncthreads();

    // ---- KV tile loader (cp.async, one commit group per call) ----
    const int krow = tid >> 1;
    const int ch0  = (tid & 1) * 4;

    {   // prologue: tile 0 -> buffer 0
        const float* kg = Kb + (size_t)(b * S_ + krow) * D_ + h * DK_;
        const float* vg = Vb + (size_t)(b * S_ + krow) * D_ + h * DK_;
#pragma unroll
        for (int i = 0; i < 4; i++) {
            int ch = ch0 + i;
            cp16(smem_u32(ks_ + (size_t)krow * AKST + ch * 4), kg + ch * 4);
            cp16(smem_u32(vs_ + (size_t)krow * AVST + ch * 4), vg + ch * 4);
        }
        asm volatile("cp.async.commit_group;" ::: "memory");
    }

    float m0 = -1e30f, m1 = -1e30f, l0 = 0.f, l1 = 0.f;
    float oa[4][4];
#pragma unroll
    for (int ni = 0; ni < 4; ni++)
#pragma unroll
        for (int r = 0; r < 4; r++) oa[ni][r] = 0.f;

    unsigned* pr = (unsigned*)ps_;
    const int ntiles = S_ / 64;

    for (int tile = 0; tile < ntiles; tile++) {
        const int s = tile & 1;

        if (tile + 1 < ntiles) {
            const int sn = s ^ 1;
            const float* kg = Kb + (size_t)(b * S_ + (tile + 1) * 64 + krow) * D_ + h * DK_;
            const float* vg = Vb + (size_t)(b * S_ + (tile + 1) * 64 + krow) * D_ + h * DK_;
#pragma unroll
            for (int i = 0; i < 4; i++) {
                int ch = ch0 + i;
                cp16(smem_u32(ks_ + (size_t)(sn * 64 + krow) * AKST + ch * 4), kg + ch * 4);
                cp16(smem_u32(vs_ + (size_t)(sn * 64 + krow) * AVST + ch * 4), vg + ch * 4);
            }
            asm volatile("cp.async.commit_group;" ::: "memory");
            asm volatile("cp.async.wait_group 1;" ::: "memory");
        } else {
            asm volatile("cp.async.wait_group 0;" ::: "memory");
        }
        __syncthreads();

        // ---- scores: S = Q K^T (K/V already tf32-rounded -> raw LDS bits) ----
        float sc[8][4];
#pragma unroll
        for (int ni = 0; ni < 8; ni++)
#pragma unroll
            for (int r = 0; r < 4; r++) sc[ni][r] = 0.f;

#pragma unroll
        for (int kt = 0; kt < 4; kt++) {
#pragma unroll
            for (int ni = 0; ni < 8; ni++) {
                unsigned b0 = ((const unsigned*)ks_)[(size_t)(s * 64 + ni * 8 + g) * AKST + kt * 8 + t];
                unsigned b1 = ((const unsigned*)ks_)[(size_t)(s * 64 + ni * 8 + g) * AKST + kt * 8 + t + 4];
                mma_tf32(sc[ni][0], sc[ni][1], sc[ni][2], sc[ni][3],
                         qf[kt][0], qf[kt][1], qf[kt][2], qf[kt][3], b0, b1);
            }
        }

        // ---- online softmax (rows g and g+8; quad = lanes sharing a row) ----
        float mx0 = -1e30f, mx1 = -1e30f;
#pragma unroll
        for (int ni = 0; ni < 8; ni++) {
            mx0 = fmaxf(mx0, fmaxf(sc[ni][0], sc[ni][1]));
            mx1 = fmaxf(mx1, fmaxf(sc[ni][2], sc[ni][3]));
        }
        mx0 = fmaxf(mx0, __shfl_xor_sync(0xffffffffu, mx0, 1));
        mx0 = fmaxf(mx0, __shfl_xor_sync(0xffffffffu, mx0, 2));
        mx1 = fmaxf(mx1, __shfl_xor_sync(0xffffffffu, mx1, 1));
        mx1 = fmaxf(mx1, __shfl_xor_sync(0xffffffffu, mx1, 2));
        const float mn0 = fmaxf(m0, mx0);
        const float mn1 = fmaxf(m1, mx1);

        float rs0 = 0.f, rs1 = 0.f;
#pragma unroll
        for (int ni = 0; ni < 8; ni++) {
            float p00 = __expf(sc[ni][0] - mn0);
            float p01 = __expf(sc[ni][1] - mn0);
            float p10 = __expf(sc[ni][2] - mn1);
            float p11 = __expf(sc[ni][3] - mn1);
            rs0 += p00 + p01;
            rs1 += p10 + p11;
            pr[(size_t)(r0 + g    ) * APST + ni * 8 + 2 * t    ] = f2tf32(p00);
            pr[(size_t)(r0 + g    ) * APST + ni * 8 + 2 * t + 1] = f2tf32(p01);
            pr[(size_t)(r0 + g + 8) * APST + ni * 8 + 2 * t    ] = f2tf32(p10);
            pr[(size_t)(r0 + g + 8) * APST + ni * 8 + 2 * t + 1] = f2tf32(p11);
        }
        rs0 += __shfl_xor_sync(0xffffffffu, rs0, 1);
        rs0 += __shfl_xor_sync(0xffffffffu, rs0, 2);
        rs1 += __shfl_xor_sync(0xffffffffu, rs1, 1);
        rs1 += __shfl_xor_sync(0xffffffffu, rs1, 2);

        const float e0 = __expf(m0 - mn0);
        const float e1 = __expf(m1 - mn1);
        l0 = l0 * e0 + rs0;
        l1 = l1 * e1 + rs1;
        m0 = mn0; m1 = mn1;
#pragma unroll
        for (int ni = 0; ni < 4; ni++) {
            oa[ni][0] *= e0; oa[ni][1] *= e0;
            oa[ni][2] *= e1; oa[ni][3] *= e1;
        }
        __syncwarp();

        // ---- O += P V ----
#pragma unroll
        for (int kk = 0; kk < 8; kk++) {
            unsigned a0 = pr[(size_t)(r0 + g    ) * APST + kk * 8 + t    ];
            unsigned a1 = pr[(size_t)(r0 + g + 8) * APST + kk * 8 + t    ];
            unsigned a2 = pr[(size_t)(r0 + g    ) * APST + kk * 8 + t + 4];
            unsigned a3 = pr[(size_t)(r0 + g + 8) * APST + kk * 8 + t + 4];
#pragma unroll
            for (int ni = 0; ni < 4; ni++) {
                unsigned b0 = ((const unsigned*)vs_)[(size_t)(s * 64 + kk * 8 + t    ) * AVST + ni * 8 + g];
                unsigned b1 = ((const unsigned*)vs_)[(size_t)(s * 64 + kk * 8 + t + 4) * AVST + ni * 8 + g];
                mma_tf32(oa[ni][0], oa[ni][1], oa[ni][2], oa[ni][3],
                         a0, a1, a2, a3, b0, b1);
            }
        }
        __syncthreads();
    }

    // ---- write O = acc / l ----
    const float inv0 = 1.f / l0;
    const float inv1 = 1.f / l1;
#pragma unroll
    for (int ni = 0; ni < 4; ni++) {
        const int cb = h * DK_ + ni * 8 + 2 * t;
        size_t ra = (size_t)(b * S_ + q0 + r0 + g    ) * D_ + cb;
        size_t rb = (size_t)(b * S_ + q0 + r0 + g + 8) * D_ + cb;
        *(float2*)&Ob[ra] = make_float2(oa[ni][0] * inv0, oa[ni][1] * inv0);
        *(float2*)&Ob[rb] = make_float2(oa[ni][2] * inv1, oa[ni][3] * inv1);
    }
}

// ============================================================================
// LayerNorm over last dim (256). One CTA per row, 256 threads.
// ============================================================================
__global__ void __launch_bounds__(256) ln_kernel(
    const float* __restrict__ X, const float* __restrict__ g,
    const float* __restrict__ b, float* __restrict__ Y)
{
    __shared__ float red[8];
    const int row = blockIdx.x;
    const int tid = threadIdx.x;
    const int lane = tid & 31, warp = tid >> 5;

    float v = X[(size_t)row * D_ + tid];
    float s = warp_sum(v);
    if (!lane) red[warp] = s;
    __syncthreads();
    if (tid < 32) {
        float t = (tid < 8) ? red[tid] : 0.f;
        t = warp_sum(t);
        if (!tid) red[0] = t;
    }
    __syncthreads();
    float mu = red[0] * (1.f / D_);
    float d = v - mu;
    float s2 = warp_sum(d * d);
    __syncthreads();
    if (!lane) red[warp] = s2;
    __syncthreads();
    if (tid < 32) {
        float t = (tid < 8) ? red[tid] : 0.f;
        t = warp_sum(t);
        if (!tid) red[0] = t;
    }
    __syncthreads();
    float var = red[0] * (1.f / D_);
    Y[(size_t)row * D_ + tid] = d * rsqrtf(var + LNEPS) * g[tid] + b[tid];
}

// ============================================================================
// host
// ============================================================================
static void run_gemm(const float* A, const float* W, const float* R, float* C,
                     int K, int O, int rnd)
{
    dim3 grid(O / 128, M_ / 128);
    gemm_mma_kernel<<<grid, 256>>>(A, W, R, C, K, O, rnd);
}

extern "C" void kernel_launch(void* const* d_in, const int* in_sizes, int n_in,
                              void* d_out, int out_size)
{
    const float* x    = (const float*)d_in[0];
    const float* W11  = (const float*)d_in[1];
    const float* W12  = (const float*)d_in[2];
    const float* W13  = (const float*)d_in[3];
    const float* W14  = (const float*)d_in[4];
    const float* W21  = (const float*)d_in[5];
    const float* W22  = (const float*)d_in[6];
    const float* W23  = (const float*)d_in[7];
    const float* W24  = (const float*)d_in[8];
    const float* Wf11 = (const float*)d_in[9];
    const float* Wf21 = (const float*)d_in[10];
    const float* Wf12 = (const float*)d_in[11];
    const float* Wf22 = (const float*)d_in[12];
    const float* g1   = (const float*)d_in[13];
    const float* b1   = (const float*)d_in[14];
    const float* g2   = (const float*)d_in[15];
    const float* b2   = (const float*)d_in[16];
    const float* g3   = (const float*)d_in[17];
    const float* b3   = (const float*)d_in[18];
    const float* g4   = (const float*)d_in[19];
    const float* b4   = (const float*)d_in[20];
    float* out = (float*)d_out;

    float *q, *k, *v, *o, *x1, *x2, *hbuf;
    cudaGetSymbolAddress((void**)&q,    g_q);
    cudaGetSymbolAddress((void**)&k,    g_k);
    cudaGetSymbolAddress((void**)&v,    g_v);
    cudaGetSymbolAddress((void**)&o,    g_o);
    cudaGetSymbolAddress((void**)&x1,   g_x1);
    cudaGetSymbolAddress((void**)&x2,   g_x2);
    cudaGetSymbolAddress((void**)&hbuf, g_h);

    cudaFuncSetAttribute(attn_mma_kernel,
                         cudaFuncAttributeMaxDynamicSharedMemorySize, ATT_SMEM);

    dim3 agrid(S_ / 64, H_, B_);

    // ---------------- block 1 ----------------
    run_gemm(x, W11, nullptr, q, D_, D_, 1);
    run_gemm(x, W12, nullptr, k, D_, D_, 1);
    run_gemm(x, W13, nullptr, v, D_, D_, 1);
    attn_mma_kernel<<<agrid, 128, ATT_SMEM>>>(q, k, v, o);
    run_gemm(o, W14, x, x1, D_, D_, 0);
    ln_kernel<<<M_, 256>>>(x1, g1, b1, x2);
    run_gemm(x2, Wf11, nullptr, hbuf, D_, DFF_, 0);
    run_gemm(hbuf, Wf21, x2, x1, DFF_, D_, 0);
    ln_kernel<<<M_, 256>>>(x1, g2, b2, x2);

    // ---------------- block 2 ----------------
    run_gemm(x2, W21, nullptr, q, D_, D_, 1);
    run_gemm(x2, W22, nullptr, k, D_, D_, 1);
    run_gemm(x2, W23, nullptr, v, D_, D_, 1);
    attn_mma_kernel<<<agrid, 128, ATT_SMEM>>>(q, k, v, o);
    run_gemm(o, W24, x2, x1, D_, D_, 0);
    ln_kernel<<<M_, 256>>>(x1, g3, b3, x2);
    run_gemm(x2, Wf12, nullptr, hbuf, D_, DFF_, 0);
    run_gemm(hbuf, Wf22, x2, x1, DFF_, D_, 0);
    ln_kernel<<<M_, 256>>>(x1, g4, b4, out);
}

// round 5
// speedup vs baseline: 2.7610x; 1.0396x over previous
#include <cuda_runtime.h>
#include <math.h>

#define B_    4
#define S_    2048
#define D_    256
#define H_    8
#define DK_   32
#define DFF_  1024
#define M_    (B_*S_)      // 8192
#define LNEPS 1e-5f

// ---------------- scratch (static device globals — allowed) ----------------
__device__ float g_q [M_*D_];
__device__ float g_k [M_*D_];
__device__ float g_v [M_*D_];
__device__ float g_o [M_*D_];
__device__ float g_x1[M_*D_];
__device__ float g_x2[M_*D_];
__device__ float g_h [M_*DFF_];

// ---------------- warp reduce helpers ----------------
__device__ __forceinline__ float warp_sum(float v) {
#pragma unroll
    for (int s = 16; s; s >>= 1) v += __shfl_xor_sync(0xffffffffu, v, s);
    return v;
}

// ---------------- PTX helpers (baseline sm_100-safe) ----------------
__device__ __forceinline__ unsigned smem_u32(const void* p) {
    unsigned a;
    asm("{ .reg .u64 t; cvta.to.shared.u64 t, %1; cvt.u32.u64 %0, t; }"
        : "=r"(a) : "l"(p));
    return a;
}
__device__ __forceinline__ void cp16(unsigned dst, const void* src) {
    asm volatile("cp.async.cg.shared.global [%0], [%1], 16;" :: "r"(dst), "l"(src));
}
__device__ __forceinline__ unsigned f2tf32(float f) {
    unsigned r;
    asm("cvt.rna.tf32.f32 %0, %1;" : "=r"(r) : "f"(f));
    return r;
}
__device__ __forceinline__ void mma_tf32(float& c0, float& c1, float& c2, float& c3,
                                         unsigned a0, unsigned a1, unsigned a2, unsigned a3,
                                         unsigned b0, unsigned b1) {
    asm volatile(
        "mma.sync.aligned.m16n8k8.row.col.f32.tf32.tf32.f32 "
        "{%0,%1,%2,%3}, {%4,%5,%6,%7}, {%8,%9}, {%0,%1,%2,%3};"
        : "+f"(c0), "+f"(c1), "+f"(c2), "+f"(c3)
        : "r"(a0), "r"(a1), "r"(a2), "r"(a3), "r"(b0), "r"(b1));
}

// ============================================================================
// tf32 mma.sync GEMM: C[M,O] = relu(A[M,K] @ W[O,K]^T) (+ R if non-null)
// BM=BN=128, BK=16. 256 threads = 8 warps (2m x 4n), warp tile 64x32.
// rnd != 0: round outputs to tf32 (rna) so consumers can feed mma without cvt.
// ============================================================================
#define GST 20   // smem row stride in floats (16 data + 4 pad)

__global__ void __launch_bounds__(256) gemm_mma_kernel(
    const float* __restrict__ A, const float* __restrict__ W,
    const float* __restrict__ R, float* __restrict__ C,
    int K, int O, int rnd)
{
    __shared__ __align__(16) float As[2][128][GST];
    __shared__ __align__(16) float Bs[2][128][GST];

    const int tid  = threadIdx.x;
    const int wid  = tid >> 5;
    const int lane = tid & 31;
    const int g    = lane >> 2;
    const int t    = lane & 3;
    const int m0 = blockIdx.y * 128;
    const int o0 = blockIdx.x * 128;
    const int wm = (wid & 1) * 64;
    const int wn = (wid >> 1) * 32;

    const unsigned sa_base = smem_u32(&As[0][0][0]);
    const unsigned sb_base = smem_u32(&Bs[0][0][0]);
    const unsigned stage_bytes = 128u * GST * 4u;

    const int lrow0 = tid >> 1;
    const int lkq0  = (tid & 1) * 2;

    float acc[4][4][4];
#pragma unroll
    for (int mi = 0; mi < 4; mi++)
#pragma unroll
        for (int ni = 0; ni < 4; ni++)
#pragma unroll
            for (int r = 0; r < 4; r++) acc[mi][ni][r] = 0.f;

    const int nk = K >> 4;

#pragma unroll
    for (int i = 0; i < 2; i++) {
        int kq = lkq0 + i;
        unsigned doff = (unsigned)(lrow0 * (GST * 4) + kq * 16);
        cp16(sa_base + doff, A + (size_t)(m0 + lrow0) * K + kq * 4);
        cp16(sb_base + doff, W + (size_t)(o0 + lrow0) * K + kq * 4);
    }
    asm volatile("cp.async.commit_group;" ::: "memory");

    for (int ki = 0; ki < nk; ki++) {
        const int s = ki & 1;

        if (ki + 1 < nk) {
            const int sn = (ki + 1) & 1;
            const int kt = (ki + 1) << 4;
#pragma unroll
            for (int i = 0; i < 2; i++) {
                int kq = lkq0 + i;
                unsigned doff = (unsigned)(sn * stage_bytes + lrow0 * (GST * 4) + kq * 16);
                cp16(sa_base + doff, A + (size_t)(m0 + lrow0) * K + kt + kq * 4);
                cp16(sb_base + doff, W + (size_t)(o0 + lrow0) * K + kt + kq * 4);
            }
            asm volatile("cp.async.commit_group;" ::: "memory");
            asm volatile("cp.async.wait_group 1;" ::: "memory");
        } else {
            asm volatile("cp.async.wait_group 0;" ::: "memory");
        }
        __syncthreads();

#pragma unroll
        for (int ks = 0; ks < 2; ks++) {
            const int k0 = ks * 8;
            unsigned af[4][4], bf[4][2];
#pragma unroll
            for (int mi = 0; mi < 4; mi++) {
                const int r = wm + mi * 16 + g;
                af[mi][0] = f2tf32(As[s][r    ][k0 + t]);
                af[mi][1] = f2tf32(As[s][r + 8][k0 + t]);
                af[mi][2] = f2tf32(As[s][r    ][k0 + t + 4]);
                af[mi][3] = f2tf32(As[s][r + 8][k0 + t + 4]);
            }
#pragma unroll
            for (int ni = 0; ni < 4; ni++) {
                const int r = wn + ni * 8 + g;
                bf[ni][0] = f2tf32(Bs[s][r][k0 + t]);
                bf[ni][1] = f2tf32(Bs[s][r][k0 + t + 4]);
            }
#pragma unroll
            for (int mi = 0; mi < 4; mi++)
#pragma unroll
                for (int ni = 0; ni < 4; ni++)
                    mma_tf32(acc[mi][ni][0], acc[mi][ni][1], acc[mi][ni][2], acc[mi][ni][3],
                             af[mi][0], af[mi][1], af[mi][2], af[mi][3],
                             bf[ni][0], bf[ni][1]);
        }
        __syncthreads();
    }

#pragma unroll
    for (int mi = 0; mi < 4; mi++) {
        const int r0 = m0 + wm + mi * 16 + g;
        const int r1 = r0 + 8;
#pragma unroll
        for (int ni = 0; ni < 4; ni++) {
            const int cb = o0 + wn + ni * 8 + 2 * t;
            float v0 = fmaxf(acc[mi][ni][0], 0.f);
            float v1 = fmaxf(acc[mi][ni][1], 0.f);
            float v2 = fmaxf(acc[mi][ni][2], 0.f);
            float v3 = fmaxf(acc[mi][ni][3], 0.f);
            if (R) {
                float2 ra = *(const float2*)&R[(size_t)r0 * O + cb];
                float2 rb = *(const float2*)&R[(size_t)r1 * O + cb];
                v0 += ra.x; v1 += ra.y; v2 += rb.x; v3 += rb.y;
            }
            if (rnd) {
                v0 = __uint_as_float(f2tf32(v0));
                v1 = __uint_as_float(f2tf32(v1));
                v2 = __uint_as_float(f2tf32(v2));
                v3 = __uint_as_float(f2tf32(v3));
            }
            *(float2*)&C[(size_t)r0 * O + cb] = make_float2(v0, v1);
            *(float2*)&C[(size_t)r1 * O + cb] = make_float2(v2, v3);
        }
    }
}

// ============================================================================
// Flash attention with tf32 mma.sync — register-resident P via shfl transpose.
// CTA = 128 thr (4 warps), 64 q rows, KV tiles of 64, double-buffered cp.async.
// Q/K/V are pre-rounded to tf32 by the producing GEMM (rnd=1).
// Smem = K + V buffers only (38912 B) -> 5 CTAs/SM (reg-limited).
// ============================================================================
#define AKST 36   // K smem row stride (floats)
#define AVST 40   // V smem row stride
#define ATT_SMEM (2*64*AKST*4 + 2*64*AVST*4)   // 38912 B

__global__ void __launch_bounds__(128) attn_mma_kernel(
    const float* __restrict__ Q, const float* __restrict__ Kb,
    const float* __restrict__ Vb, float* __restrict__ Ob)
{
    extern __shared__ __align__(16) float dsm[];
    float* ks_ = dsm;                  // [2][64][AKST]
    float* vs_ = dsm + 2 * 64 * AKST;  // [2][64][AVST]

    const int tid  = threadIdx.x;
    const int lane = tid & 31;
    const int warp = tid >> 5;
    const int g = lane >> 2;
    const int t = lane & 3;
    const int b = blockIdx.z, h = blockIdx.y;
    const int q0 = blockIdx.x * 64;
    const int r0 = warp * 16;
    const float scale = 0.17677669529663687f;   // 1/sqrt(32)

    // ---- Q fragments straight from gmem (one-time; Q pre-rounded to tf32) ----
    unsigned qf[4][4];
    {
        const float* qrow0 = Q + (size_t)(b * S_ + q0 + r0 + g    ) * D_ + h * DK_;
        const float* qrow1 = Q + (size_t)(b * S_ + q0 + r0 + g + 8) * D_ + h * DK_;
#pragma unroll
        for (int kt = 0; kt < 4; kt++) {
            qf[kt][0] = f2tf32(qrow0[kt * 8 + t    ] * scale);
            qf[kt][1] = f2tf32(qrow1[kt * 8 + t    ] * scale);
            qf[kt][2] = f2tf32(qrow0[kt * 8 + t + 4] * scale);
            qf[kt][3] = f2tf32(qrow1[kt * 8 + t + 4] * scale);
        }
    }

    // ---- KV tile loader (cp.async) ----
    const int krow = tid >> 1;
    const int ch0  = (tid & 1) * 4;

    {   // prologue: tile 0 -> buffer 0
        const float* kg = Kb + (size_t)(b * S_ + krow) * D_ + h * DK_;
        const float* vg = Vb + (size_t)(b * S_ + krow) * D_ + h * DK_;
#pragma unroll
        for (int i = 0; i < 4; i++) {
            int ch = ch0 + i;
            cp16(smem_u32(ks_ + (size_t)krow * AKST + ch * 4), kg + ch * 4);
            cp16(smem_u32(vs_ + (size_t)krow * AVST + ch * 4), vg + ch * 4);
        }
        asm volatile("cp.async.commit_group;" ::: "memory");
    }

    float m0 = -1e30f, m1 = -1e30f, l0 = 0.f, l1 = 0.f;
    float oa[4][4];
#pragma unroll
    for (int ni = 0; ni < 4; ni++)
#pragma unroll
        for (int r = 0; r < 4; r++) oa[ni][r] = 0.f;

    const int ntiles = S_ / 64;

    for (int tile = 0; tile < ntiles; tile++) {
        const int s = tile & 1;

        if (tile + 1 < ntiles) {
            const int sn = s ^ 1;
            const float* kg = Kb + (size_t)(b * S_ + (tile + 1) * 64 + krow) * D_ + h * DK_;
            const float* vg = Vb + (size_t)(b * S_ + (tile + 1) * 64 + krow) * D_ + h * DK_;
#pragma unroll
            for (int i = 0; i < 4; i++) {
                int ch = ch0 + i;
                cp16(smem_u32(ks_ + (size_t)(sn * 64 + krow) * AKST + ch * 4), kg + ch * 4);
                cp16(smem_u32(vs_ + (size_t)(sn * 64 + krow) * AVST + ch * 4), vg + ch * 4);
            }
            asm volatile("cp.async.commit_group;" ::: "memory");
            asm volatile("cp.async.wait_group 1;" ::: "memory");
        } else {
            asm volatile("cp.async.wait_group 0;" ::: "memory");
        }
        __syncthreads();

        // ---- scores: S = Q K^T ----
        float sc[8][4];
#pragma unroll
        for (int ni = 0; ni < 8; ni++)
#pragma unroll
            for (int r = 0; r < 4; r++) sc[ni][r] = 0.f;

#pragma unroll
        for (int kt = 0; kt < 4; kt++) {
#pragma unroll
            for (int ni = 0; ni < 8; ni++) {
                unsigned b0 = ((const unsigned*)ks_)[(size_t)(s * 64 + ni * 8 + g) * AKST + kt * 8 + t];
                unsigned b1 = ((const unsigned*)ks_)[(size_t)(s * 64 + ni * 8 + g) * AKST + kt * 8 + t + 4];
                mma_tf32(sc[ni][0], sc[ni][1], sc[ni][2], sc[ni][3],
                         qf[kt][0], qf[kt][1], qf[kt][2], qf[kt][3], b0, b1);
            }
        }

        // ---- row max (rows g and g+8; quad lanes share a row) ----
        float mx0 = -1e30f, mx1 = -1e30f;
#pragma unroll
        for (int ni = 0; ni < 8; ni++) {
            mx0 = fmaxf(mx0, fmaxf(sc[ni][0], sc[ni][1]));
            mx1 = fmaxf(mx1, fmaxf(sc[ni][2], sc[ni][3]));
        }
        mx0 = fmaxf(mx0, __shfl_xor_sync(0xffffffffu, mx0, 1));
        mx0 = fmaxf(mx0, __shfl_xor_sync(0xffffffffu, mx0, 2));
        mx1 = fmaxf(mx1, __shfl_xor_sync(0xffffffffu, mx1, 1));
        mx1 = fmaxf(mx1, __shfl_xor_sync(0xffffffffu, mx1, 2));
        const float mn0 = fmaxf(m0, mx0);
        const float mn1 = fmaxf(m1, mx1);
        const float e0 = __expf(m0 - mn0);
        const float e1 = __expf(m1 - mn1);
        m0 = mn0; m1 = mn1;
#pragma unroll
        for (int ni = 0; ni < 4; ni++) {
            oa[ni][0] *= e0; oa[ni][1] *= e0;
            oa[ni][2] *= e1; oa[ni][3] *= e1;
        }

        // ---- per score tile: exp -> shfl-transpose C-frag to A-frag -> PV mma ----
        const int sl0 = 4 * g + (t >> 1);
        const int sl1 = sl0 + 2;
        const bool odd = (t & 1);
        float rs0 = 0.f, rs1 = 0.f;

#pragma unroll
        for (int kk = 0; kk < 8; kk++) {
            float p00 = __expf(sc[kk][0] - mn0);
            float p01 = __expf(sc[kk][1] - mn0);
            float p10 = __expf(sc[kk][2] - mn1);
            float p11 = __expf(sc[kk][3] - mn1);
            rs0 += p00 + p01;
            rs1 += p10 + p11;

            unsigned u00 = f2tf32(p00), u01 = f2tf32(p01);
            unsigned u10 = f2tf32(p10), u11 = f2tf32(p11);

            unsigned x00 = __shfl_sync(0xffffffffu, u00, sl0);
            unsigned x01 = __shfl_sync(0xffffffffu, u01, sl0);
            unsigned x10 = __shfl_sync(0xffffffffu, u10, sl0);
            unsigned x11 = __shfl_sync(0xffffffffu, u11, sl0);
            unsigned y00 = __shfl_sync(0xffffffffu, u00, sl1);
            unsigned y01 = __shfl_sync(0xffffffffu, u01, sl1);
            unsigned y10 = __shfl_sync(0xffffffffu, u10, sl1);
            unsigned y11 = __shfl_sync(0xffffffffu, u11, sl1);

            unsigned a0 = odd ? x01 : x00;   // P[g   ][t]
            unsigned a1 = odd ? x11 : x10;   // P[g+8 ][t]
            unsigned a2 = odd ? y01 : y00;   // P[g   ][t+4]
            unsigned a3 = odd ? y11 : y10;   // P[g+8 ][t+4]

#pragma unroll
            for (int ni = 0; ni < 4; ni++) {
                unsigned b0 = ((const unsigned*)vs_)[(size_t)(s * 64 + kk * 8 + t    ) * AVST + ni * 8 + g];
                unsigned b1 = ((const unsigned*)vs_)[(size_t)(s * 64 + kk * 8 + t + 4) * AVST + ni * 8 + g];
                mma_tf32(oa[ni][0], oa[ni][1], oa[ni][2], oa[ni][3],
                         a0, a1, a2, a3, b0, b1);
            }
        }

        rs0 += __shfl_xor_sync(0xffffffffu, rs0, 1);
        rs0 += __shfl_xor_sync(0xffffffffu, rs0, 2);
        rs1 += __shfl_xor_sync(0xffffffffu, rs1, 1);
        rs1 += __shfl_xor_sync(0xffffffffu, rs1, 2);
        l0 = l0 * e0 + rs0;
        l1 = l1 * e1 + rs1;

        __syncthreads();
    }

    // ---- write O = acc / l ----
    const float inv0 = 1.f / l0;
    const float inv1 = 1.f / l1;
#pragma unroll
    for (int ni = 0; ni < 4; ni++) {
        const int cb = h * DK_ + ni * 8 + 2 * t;
        size_t ra = (size_t)(b * S_ + q0 + r0 + g    ) * D_ + cb;
        size_t rb = (size_t)(b * S_ + q0 + r0 + g + 8) * D_ + cb;
        *(float2*)&Ob[ra] = make_float2(oa[ni][0] * inv0, oa[ni][1] * inv0);
        *(float2*)&Ob[rb] = make_float2(oa[ni][2] * inv1, oa[ni][3] * inv1);
    }
}

// ============================================================================
// LayerNorm over last dim (256). One CTA per row, 256 threads.
// ============================================================================
__global__ void __launch_bounds__(256) ln_kernel(
    const float* __restrict__ X, const float* __restrict__ g,
    const float* __restrict__ b, float* __restrict__ Y)
{
    __shared__ float red[8];
    const int row = blockIdx.x;
    const int tid = threadIdx.x;
    const int lane = tid & 31, warp = tid >> 5;

    float v = X[(size_t)row * D_ + tid];
    float s = warp_sum(v);
    if (!lane) red[warp] = s;
    __syncthreads();
    if (tid < 32) {
        float t = (tid < 8) ? red[tid] : 0.f;
        t = warp_sum(t);
        if (!tid) red[0] = t;
    }
    __syncthreads();
    float mu = red[0] * (1.f / D_);
    float d = v - mu;
    float s2 = warp_sum(d * d);
    __syncthreads();
    if (!lane) red[warp] = s2;
    __syncthreads();
    if (tid < 32) {
        float t = (tid < 8) ? red[tid] : 0.f;
        t = warp_sum(t);
        if (!tid) red[0] = t;
    }
    __syncthreads();
    float var = red[0] * (1.f / D_);
    Y[(size_t)row * D_ + tid] = d * rsqrtf(var + LNEPS) * g[tid] + b[tid];
}

// ============================================================================
// host
// ============================================================================
static void run_gemm(const float* A, const float* W, const float* R, float* C,
                     int K, int O, int rnd)
{
    dim3 grid(O / 128, M_ / 128);
    gemm_mma_kernel<<<grid, 256>>>(A, W, R, C, K, O, rnd);
}

extern "C" void kernel_launch(void* const* d_in, const int* in_sizes, int n_in,
                              void* d_out, int out_size)
{
    const float* x    = (const float*)d_in[0];
    const float* W11  = (const float*)d_in[1];
    const float* W12  = (const float*)d_in[2];
    const float* W13  = (const float*)d_in[3];
    const float* W14  = (const float*)d_in[4];
    const float* W21  = (const float*)d_in[5];
    const float* W22  = (const float*)d_in[6];
    const float* W23  = (const float*)d_in[7];
    const float* W24  = (const float*)d_in[8];
    const float* Wf11 = (const float*)d_in[9];
    const float* Wf21 = (const float*)d_in[10];
    const float* Wf12 = (const float*)d_in[11];
    const float* Wf22 = (const float*)d_in[12];
    const float* g1   = (const float*)d_in[13];
    const float* b1   = (const float*)d_in[14];
    const float* g2   = (const float*)d_in[15];
    const float* b2   = (const float*)d_in[16];
    const float* g3   = (const float*)d_in[17];
    const float* b3   = (const float*)d_in[18];
    const float* g4   = (const float*)d_in[19];
    const float* b4   = (const float*)d_in[20];
    float* out = (float*)d_out;

    float *q, *k, *v, *o, *x1, *x2, *hbuf;
    cudaGetSymbolAddress((void**)&q,    g_q);
    cudaGetSymbolAddress((void**)&k,    g_k);
    cudaGetSymbolAddress((void**)&v,    g_v);
    cudaGetSymbolAddress((void**)&o,    g_o);
    cudaGetSymbolAddress((void**)&x1,   g_x1);
    cudaGetSymbolAddress((void**)&x2,   g_x2);
    cudaGetSymbolAddress((void**)&hbuf, g_h);

    cudaFuncSetAttribute(attn_mma_kernel,
                         cudaFuncAttributeMaxDynamicSharedMemorySize, ATT_SMEM);

    dim3 agrid(S_ / 64, H_, B_);

    // ---------------- block 1 ----------------
    run_gemm(x, W11, nullptr, q, D_, D_, 1);
    run_gemm(x, W12, nullptr, k, D_, D_, 1);
    run_gemm(x, W13, nullptr, v, D_, D_, 1);
    attn_mma_kernel<<<agrid, 128, ATT_SMEM>>>(q, k, v, o);
    run_gemm(o, W14, x, x1, D_, D_, 0);
    ln_kernel<<<M_, 256>>>(x1, g1, b1, x2);
    run_gemm(x2, Wf11, nullptr, hbuf, D_, DFF_, 0);
    run_gemm(hbuf, Wf21, x2, x1, DFF_, D_, 0);
    ln_kernel<<<M_, 256>>>(x1, g2, b2, x2);

    // ---------------- block 2 ----------------
    run_gemm(x2, W21, nullptr, q, D_, D_, 1);
    run_gemm(x2, W22, nullptr, k, D_, D_, 1);
    run_gemm(x2, W23, nullptr, v, D_, D_, 1);
    attn_mma_kernel<<<agrid, 128, ATT_SMEM>>>(q, k, v, o);
    run_gemm(o, W24, x2, x1, D_, D_, 0);
    ln_kernel<<<M_, 256>>>(x1, g3, b3, x2);
    run_gemm(x2, Wf12, nullptr, hbuf, D_, DFF_, 0);
    run_gemm(hbuf, Wf22, x2, x1, DFF_, D_, 0);
    ln_kernel<<<M_, 256>>>(x1, g4, b4, out);
}

// round 6
// speedup vs baseline: 2.9352x; 1.0631x over previous
#include <cuda_runtime.h>
#include <math.h>

#define B_    4
#define S_    2048
#define D_    256
#define H_    8
#define DK_   32
#define DFF_  1024
#define M_    (B_*S_)      // 8192
#define LNEPS 1e-5f

// ---------------- scratch (static device globals — allowed) ----------------
__device__ float g_q [M_*D_];
__device__ float g_k [M_*D_];
__device__ float g_v [M_*D_];
__device__ float g_o [M_*D_];
__device__ float g_x1[M_*D_];
__device__ float g_x2[M_*D_];
__device__ float g_h [M_*DFF_];

// ---------------- warp reduce helpers ----------------
__device__ __forceinline__ float warp_sum(float v) {
#pragma unroll
    for (int s = 16; s; s >>= 1) v += __shfl_xor_sync(0xffffffffu, v, s);
    return v;
}

// ---------------- PTX helpers (baseline sm_100-safe) ----------------
__device__ __forceinline__ unsigned smem_u32(const void* p) {
    unsigned a;
    asm("{ .reg .u64 t; cvta.to.shared.u64 t, %1; cvt.u32.u64 %0, t; }"
        : "=r"(a) : "l"(p));
    return a;
}
__device__ __forceinline__ void cp16(unsigned dst, const void* src) {
    asm volatile("cp.async.cg.shared.global [%0], [%1], 16;" :: "r"(dst), "l"(src));
}
__device__ __forceinline__ unsigned f2tf32(float f) {
    unsigned r;
    asm("cvt.rna.tf32.f32 %0, %1;" : "=r"(r) : "f"(f));
    return r;
}
__device__ __forceinline__ void mma_tf32(float& c0, float& c1, float& c2, float& c3,
                                         unsigned a0, unsigned a1, unsigned a2, unsigned a3,
                                         unsigned b0, unsigned b1) {
    asm volatile(
        "mma.sync.aligned.m16n8k8.row.col.f32.tf32.tf32.f32 "
        "{%0,%1,%2,%3}, {%4,%5,%6,%7}, {%8,%9}, {%0,%1,%2,%3};"
        : "+f"(c0), "+f"(c1), "+f"(c2), "+f"(c3)
        : "r"(a0), "r"(a1), "r"(a2), "r"(a3), "r"(b0), "r"(b1));
}

// ============================================================================
// tf32 mma.sync GEMM: C[M,O] = relu(A[M,K] @ W[O,K]^T) (+ R if non-null)
// BM=BN=128, BK=16. 256 threads = 8 warps (2m x 4n), warp tile 64x32.
// rnd != 0: round outputs to tf32 (rna) so consumers can feed mma without cvt.
// ============================================================================
#define GST 20   // smem row stride in floats (16 data + 4 pad)

__device__ __forceinline__ void gemm_mma_body(
    const float* __restrict__ A, const float* __restrict__ W,
    const float* __restrict__ R, float* __restrict__ C,
    int K, int O, int rnd)
{
    __shared__ __align__(16) float As[2][128][GST];
    __shared__ __align__(16) float Bs[2][128][GST];

    const int tid  = threadIdx.x;
    const int wid  = tid >> 5;
    const int lane = tid & 31;
    const int g    = lane >> 2;
    const int t    = lane & 3;
    const int m0 = blockIdx.y * 128;
    const int o0 = blockIdx.x * 128;
    const int wm = (wid & 1) * 64;
    const int wn = (wid >> 1) * 32;

    const unsigned sa_base = smem_u32(&As[0][0][0]);
    const unsigned sb_base = smem_u32(&Bs[0][0][0]);
    const unsigned stage_bytes = 128u * GST * 4u;

    const int lrow0 = tid >> 1;
    const int lkq0  = (tid & 1) * 2;

    float acc[4][4][4];
#pragma unroll
    for (int mi = 0; mi < 4; mi++)
#pragma unroll
        for (int ni = 0; ni < 4; ni++)
#pragma unroll
            for (int r = 0; r < 4; r++) acc[mi][ni][r] = 0.f;

    const int nk = K >> 4;

#pragma unroll
    for (int i = 0; i < 2; i++) {
        int kq = lkq0 + i;
        unsigned doff = (unsigned)(lrow0 * (GST * 4) + kq * 16);
        cp16(sa_base + doff, A + (size_t)(m0 + lrow0) * K + kq * 4);
        cp16(sb_base + doff, W + (size_t)(o0 + lrow0) * K + kq * 4);
    }
    asm volatile("cp.async.commit_group;" ::: "memory");

    for (int ki = 0; ki < nk; ki++) {
        const int s = ki & 1;

        if (ki + 1 < nk) {
            const int sn = (ki + 1) & 1;
            const int kt = (ki + 1) << 4;
#pragma unroll
            for (int i = 0; i < 2; i++) {
                int kq = lkq0 + i;
                unsigned doff = (unsigned)(sn * stage_bytes + lrow0 * (GST * 4) + kq * 16);
                cp16(sa_base + doff, A + (size_t)(m0 + lrow0) * K + kt + kq * 4);
                cp16(sb_base + doff, W + (size_t)(o0 + lrow0) * K + kt + kq * 4);
            }
            asm volatile("cp.async.commit_group;" ::: "memory");
            asm volatile("cp.async.wait_group 1;" ::: "memory");
        } else {
            asm volatile("cp.async.wait_group 0;" ::: "memory");
        }
        __syncthreads();

#pragma unroll
        for (int ks = 0; ks < 2; ks++) {
            const int k0 = ks * 8;
            unsigned af[4][4], bf[4][2];
#pragma unroll
            for (int mi = 0; mi < 4; mi++) {
                const int r = wm + mi * 16 + g;
                af[mi][0] = f2tf32(As[s][r    ][k0 + t]);
                af[mi][1] = f2tf32(As[s][r + 8][k0 + t]);
                af[mi][2] = f2tf32(As[s][r    ][k0 + t + 4]);
                af[mi][3] = f2tf32(As[s][r + 8][k0 + t + 4]);
            }
#pragma unroll
            for (int ni = 0; ni < 4; ni++) {
                const int r = wn + ni * 8 + g;
                bf[ni][0] = f2tf32(Bs[s][r][k0 + t]);
                bf[ni][1] = f2tf32(Bs[s][r][k0 + t + 4]);
            }
#pragma unroll
            for (int mi = 0; mi < 4; mi++)
#pragma unroll
                for (int ni = 0; ni < 4; ni++)
                    mma_tf32(acc[mi][ni][0], acc[mi][ni][1], acc[mi][ni][2], acc[mi][ni][3],
                             af[mi][0], af[mi][1], af[mi][2], af[mi][3],
                             bf[ni][0], bf[ni][1]);
        }
        __syncthreads();
    }

#pragma unroll
    for (int mi = 0; mi < 4; mi++) {
        const int r0 = m0 + wm + mi * 16 + g;
        const int r1 = r0 + 8;
#pragma unroll
        for (int ni = 0; ni < 4; ni++) {
            const int cb = o0 + wn + ni * 8 + 2 * t;
            float v0 = fmaxf(acc[mi][ni][0], 0.f);
            float v1 = fmaxf(acc[mi][ni][1], 0.f);
            float v2 = fmaxf(acc[mi][ni][2], 0.f);
            float v3 = fmaxf(acc[mi][ni][3], 0.f);
            if (R) {
                float2 ra = *(const float2*)&R[(size_t)r0 * O + cb];
                float2 rb = *(const float2*)&R[(size_t)r1 * O + cb];
                v0 += ra.x; v1 += ra.y; v2 += rb.x; v3 += rb.y;
            }
            if (rnd) {
                v0 = __uint_as_float(f2tf32(v0));
                v1 = __uint_as_float(f2tf32(v1));
                v2 = __uint_as_float(f2tf32(v2));
                v3 = __uint_as_float(f2tf32(v3));
            }
            *(float2*)&C[(size_t)r0 * O + cb] = make_float2(v0, v1);
            *(float2*)&C[(size_t)r1 * O + cb] = make_float2(v2, v3);
        }
    }
}

__global__ void __launch_bounds__(256) gemm_mma_kernel(
    const float* __restrict__ A, const float* __restrict__ W,
    const float* __restrict__ R, float* __restrict__ C,
    int K, int O, int rnd)
{
    gemm_mma_body(A, W, R, C, K, O, rnd);
}

// Batched QKV projection: blockIdx.z selects (W, C) pair. rnd=1.
__global__ void __launch_bounds__(256) gemm_qkv_kernel(
    const float* __restrict__ A,
    const float* __restrict__ Wq, const float* __restrict__ Wk, const float* __restrict__ Wv,
    float* __restrict__ Cq, float* __restrict__ Ck, float* __restrict__ Cv)
{
    const float* W = (blockIdx.z == 0) ? Wq : (blockIdx.z == 1) ? Wk : Wv;
    float*       C = (blockIdx.z == 0) ? Cq : (blockIdx.z == 1) ? Ck : Cv;
    gemm_mma_body(A, W, nullptr, C, D_, D_, 1);
}

// ============================================================================
// Flash attention, tf32 mma.sync, 2 row-blocks per warp (32 q rows/warp).
// CTA = 128 thr (4 warps) = 128 q rows. KV tiles of 64, double-buffered.
// K fragment pair feeds 2 MMAs (both row blocks) -> LDS per MMA halved.
// ============================================================================
#define AKST 36   // K smem row stride (floats)
#define AVST 40   // V smem row stride
#define ATT_SMEM (2*64*AKST*4 + 2*64*AVST*4)   // 38912 B

__global__ void __launch_bounds__(128, 3) attn_mma_kernel(
    const float* __restrict__ Q, const float* __restrict__ Kb,
    const float* __restrict__ Vb, float* __restrict__ Ob)
{
    extern __shared__ __align__(16) float dsm[];
    float* ks_ = dsm;                  // [2][64][AKST]
    float* vs_ = dsm + 2 * 64 * AKST;  // [2][64][AVST]

    const int tid  = threadIdx.x;
    const int lane = tid & 31;
    const int warp = tid >> 5;
    const int g = lane >> 2;
    const int t = lane & 3;
    const int b = blockIdx.z, h = blockIdx.y;
    const int q0 = blockIdx.x * 128;
    const int r0 = warp * 32;
    const float scale = 0.17677669529663687f;   // 1/sqrt(32)

    // ---- Q fragments (2 row blocks) straight from gmem, pre-rounded tf32 ----
    unsigned qf[2][4][4];
#pragma unroll
    for (int rb = 0; rb < 2; rb++) {
        const float* qrow0 = Q + (size_t)(b * S_ + q0 + r0 + rb * 16 + g    ) * D_ + h * DK_;
        const float* qrow1 = Q + (size_t)(b * S_ + q0 + r0 + rb * 16 + g + 8) * D_ + h * DK_;
#pragma unroll
        for (int kt = 0; kt < 4; kt++) {
            qf[rb][kt][0] = f2tf32(qrow0[kt * 8 + t    ] * scale);
            qf[rb][kt][1] = f2tf32(qrow1[kt * 8 + t    ] * scale);
            qf[rb][kt][2] = f2tf32(qrow0[kt * 8 + t + 4] * scale);
            qf[rb][kt][3] = f2tf32(qrow1[kt * 8 + t + 4] * scale);
        }
    }

    // ---- KV tile loader (cp.async) ----
    const int krow = tid >> 1;
    const int ch0  = (tid & 1) * 4;

    {   // prologue: tile 0 -> buffer 0
        const float* kg = Kb + (size_t)(b * S_ + krow) * D_ + h * DK_;
        const float* vg = Vb + (size_t)(b * S_ + krow) * D_ + h * DK_;
#pragma unroll
        for (int i = 0; i < 4; i++) {
            int ch = ch0 + i;
            cp16(smem_u32(ks_ + (size_t)krow * AKST + ch * 4), kg + ch * 4);
            cp16(smem_u32(vs_ + (size_t)krow * AVST + ch * 4), vg + ch * 4);
        }
        asm volatile("cp.async.commit_group;" ::: "memory");
    }

    float m_[2][2], l_[2][2];
    float oa[2][4][4];
#pragma unroll
    for (int rb = 0; rb < 2; rb++) {
        m_[rb][0] = -1e30f; m_[rb][1] = -1e30f;
        l_[rb][0] = 0.f;    l_[rb][1] = 0.f;
#pragma unroll
        for (int ni = 0; ni < 4; ni++)
#pragma unroll
            for (int r = 0; r < 4; r++) oa[rb][ni][r] = 0.f;
    }

    const int ntiles = S_ / 64;
    const int sl0 = 4 * g + (t >> 1);
    const int sl1 = sl0 + 2;
    const bool odd = (t & 1);

    for (int tile = 0; tile < ntiles; tile++) {
        const int s = tile & 1;

        if (tile + 1 < ntiles) {
            const int sn = s ^ 1;
            const float* kg = Kb + (size_t)(b * S_ + (tile + 1) * 64 + krow) * D_ + h * DK_;
            const float* vg = Vb + (size_t)(b * S_ + (tile + 1) * 64 + krow) * D_ + h * DK_;
#pragma unroll
            for (int i = 0; i < 4; i++) {
                int ch = ch0 + i;
                cp16(smem_u32(ks_ + (size_t)(sn * 64 + krow) * AKST + ch * 4), kg + ch * 4);
                cp16(smem_u32(vs_ + (size_t)(sn * 64 + krow) * AVST + ch * 4), vg + ch * 4);
            }
            asm volatile("cp.async.commit_group;" ::: "memory");
            asm volatile("cp.async.wait_group 1;" ::: "memory");
        } else {
            asm volatile("cp.async.wait_group 0;" ::: "memory");
        }
        __syncthreads();

        // ---- scores for both row blocks: each K fragment feeds 2 MMAs ----
        float sc[2][8][4];
#pragma unroll
        for (int rb = 0; rb < 2; rb++)
#pragma unroll
            for (int ni = 0; ni < 8; ni++)
#pragma unroll
                for (int r = 0; r < 4; r++) sc[rb][ni][r] = 0.f;

#pragma unroll
        for (int kt = 0; kt < 4; kt++) {
#pragma unroll
            for (int ni = 0; ni < 8; ni++) {
                unsigned b0 = ((const unsigned*)ks_)[(size_t)(s * 64 + ni * 8 + g) * AKST + kt * 8 + t];
                unsigned b1 = ((const unsigned*)ks_)[(size_t)(s * 64 + ni * 8 + g) * AKST + kt * 8 + t + 4];
                mma_tf32(sc[0][ni][0], sc[0][ni][1], sc[0][ni][2], sc[0][ni][3],
                         qf[0][kt][0], qf[0][kt][1], qf[0][kt][2], qf[0][kt][3], b0, b1);
                mma_tf32(sc[1][ni][0], sc[1][ni][1], sc[1][ni][2], sc[1][ni][3],
                         qf[1][kt][0], qf[1][kt][1], qf[1][kt][2], qf[1][kt][3], b0, b1);
            }
        }

        // ---- online softmax state update per row block ----
        float mn[2][2], e[2][2];
#pragma unroll
        for (int rb = 0; rb < 2; rb++) {
            float mx0 = -1e30f, mx1 = -1e30f;
#pragma unroll
            for (int ni = 0; ni < 8; ni++) {
                mx0 = fmaxf(mx0, fmaxf(sc[rb][ni][0], sc[rb][ni][1]));
                mx1 = fmaxf(mx1, fmaxf(sc[rb][ni][2], sc[rb][ni][3]));
            }
            mx0 = fmaxf(mx0, __shfl_xor_sync(0xffffffffu, mx0, 1));
            mx0 = fmaxf(mx0, __shfl_xor_sync(0xffffffffu, mx0, 2));
            mx1 = fmaxf(mx1, __shfl_xor_sync(0xffffffffu, mx1, 1));
            mx1 = fmaxf(mx1, __shfl_xor_sync(0xffffffffu, mx1, 2));
            mn[rb][0] = fmaxf(m_[rb][0], mx0);
            mn[rb][1] = fmaxf(m_[rb][1], mx1);
            e[rb][0] = __expf(m_[rb][0] - mn[rb][0]);
            e[rb][1] = __expf(m_[rb][1] - mn[rb][1]);
            m_[rb][0] = mn[rb][0]; m_[rb][1] = mn[rb][1];
#pragma unroll
            for (int ni = 0; ni < 4; ni++) {
                oa[rb][ni][0] *= e[rb][0]; oa[rb][ni][1] *= e[rb][0];
                oa[rb][ni][2] *= e[rb][1]; oa[rb][ni][3] *= e[rb][1];
            }
        }

        // ---- exp -> shfl-transpose -> PV (V fragment feeds 2 MMAs) ----
        float rs[2][2] = {{0.f, 0.f}, {0.f, 0.f}};

#pragma unroll
        for (int kk = 0; kk < 8; kk++) {
            unsigned a_[2][4];
#pragma unroll
            for (int rb = 0; rb < 2; rb++) {
                float p00 = __expf(sc[rb][kk][0] - mn[rb][0]);
                float p01 = __expf(sc[rb][kk][1] - mn[rb][0]);
                float p10 = __expf(sc[rb][kk][2] - mn[rb][1]);
                float p11 = __expf(sc[rb][kk][3] - mn[rb][1]);
                rs[rb][0] += p00 + p01;
                rs[rb][1] += p10 + p11;

                unsigned u00 = f2tf32(p00), u01 = f2tf32(p01);
                unsigned u10 = f2tf32(p10), u11 = f2tf32(p11);

                unsigned x00 = __shfl_sync(0xffffffffu, u00, sl0);
                unsigned x01 = __shfl_sync(0xffffffffu, u01, sl0);
                unsigned x10 = __shfl_sync(0xffffffffu, u10, sl0);
                unsigned x11 = __shfl_sync(0xffffffffu, u11, sl0);
                unsigned y00 = __shfl_sync(0xffffffffu, u00, sl1);
                unsigned y01 = __shfl_sync(0xffffffffu, u01, sl1);
                unsigned y10 = __shfl_sync(0xffffffffu, u10, sl1);
                unsigned y11 = __shfl_sync(0xffffffffu, u11, sl1);

                a_[rb][0] = odd ? x01 : x00;
                a_[rb][1] = odd ? x11 : x10;
                a_[rb][2] = odd ? y01 : y00;
                a_[rb][3] = odd ? y11 : y10;
            }

#pragma unroll
            for (int ni = 0; ni < 4; ni++) {
                unsigned b0 = ((const unsigned*)vs_)[(size_t)(s * 64 + kk * 8 + t    ) * AVST + ni * 8 + g];
                unsigned b1 = ((const unsigned*)vs_)[(size_t)(s * 64 + kk * 8 + t + 4) * AVST + ni * 8 + g];
                mma_tf32(oa[0][ni][0], oa[0][ni][1], oa[0][ni][2], oa[0][ni][3],
                         a_[0][0], a_[0][1], a_[0][2], a_[0][3], b0, b1);
                mma_tf32(oa[1][ni][0], oa[1][ni][1], oa[1][ni][2], oa[1][ni][3],
                         a_[1][0], a_[1][1], a_[1][2], a_[1][3], b0, b1);
            }
        }

#pragma unroll
        for (int rb = 0; rb < 2; rb++) {
            float r0s = rs[rb][0], r1s = rs[rb][1];
            r0s += __shfl_xor_sync(0xffffffffu, r0s, 1);
            r0s += __shfl_xor_sync(0xffffffffu, r0s, 2);
            r1s += __shfl_xor_sync(0xffffffffu, r1s, 1);
            r1s += __shfl_xor_sync(0xffffffffu, r1s, 2);
            l_[rb][0] = l_[rb][0] * e[rb][0] + r0s;
            l_[rb][1] = l_[rb][1] * e[rb][1] + r1s;
        }

        __syncthreads();
    }

    // ---- write O = acc / l ----
#pragma unroll
    for (int rb = 0; rb < 2; rb++) {
        const float inv0 = 1.f / l_[rb][0];
        const float inv1 = 1.f / l_[rb][1];
#pragma unroll
        for (int ni = 0; ni < 4; ni++) {
            const int cb = h * DK_ + ni * 8 + 2 * t;
            size_t ra = (size_t)(b * S_ + q0 + r0 + rb * 16 + g    ) * D_ + cb;
            size_t rx = (size_t)(b * S_ + q0 + r0 + rb * 16 + g + 8) * D_ + cb;
            *(float2*)&Ob[ra] = make_float2(oa[rb][ni][0] * inv0, oa[rb][ni][1] * inv0);
            *(float2*)&Ob[rx] = make_float2(oa[rb][ni][2] * inv1, oa[rb][ni][3] * inv1);
        }
    }
}

// ============================================================================
// LayerNorm over last dim (256). One CTA per row, 256 threads.
// ============================================================================
__global__ void __launch_bounds__(256) ln_kernel(
    const float* __restrict__ X, const float* __restrict__ g,
    const float* __restrict__ b, float* __restrict__ Y)
{
    __shared__ float red[8];
    const int row = blockIdx.x;
    const int tid = threadIdx.x;
    const int lane = tid & 31, warp = tid >> 5;

    float v = X[(size_t)row * D_ + tid];
    float s = warp_sum(v);
    if (!lane) red[warp] = s;
    __syncthreads();
    if (tid < 32) {
        float t = (tid < 8) ? red[tid] : 0.f;
        t = warp_sum(t);
        if (!tid) red[0] = t;
    }
    __syncthreads();
    float mu = red[0] * (1.f / D_);
    float d = v - mu;
    float s2 = warp_sum(d * d);
    __syncthreads();
    if (!lane) red[warp] = s2;
    __syncthreads();
    if (tid < 32) {
        float t = (tid < 8) ? red[tid] : 0.f;
        t = warp_sum(t);
        if (!tid) red[0] = t;
    }
    __syncthreads();
    float var = red[0] * (1.f / D_);
    Y[(size_t)row * D_ + tid] = d * rsqrtf(var + LNEPS) * g[tid] + b[tid];
}

// ============================================================================
// host
// ============================================================================
static void run_gemm(const float* A, const float* W, const float* R, float* C,
                     int K, int O, int rnd)
{
    dim3 grid(O / 128, M_ / 128);
    gemm_mma_kernel<<<grid, 256>>>(A, W, R, C, K, O, rnd);
}

extern "C" void kernel_launch(void* const* d_in, const int* in_sizes, int n_in,
                              void* d_out, int out_size)
{
    const float* x    = (const float*)d_in[0];
    const float* W11  = (const float*)d_in[1];
    const float* W12  = (const float*)d_in[2];
    const float* W13  = (const float*)d_in[3];
    const float* W14  = (const float*)d_in[4];
    const float* W21  = (const float*)d_in[5];
    const float* W22  = (const float*)d_in[6];
    const float* W23  = (const float*)d_in[7];
    const float* W24  = (const float*)d_in[8];
    const float* Wf11 = (const float*)d_in[9];
    const float* Wf21 = (const float*)d_in[10];
    const float* Wf12 = (const float*)d_in[11];
    const float* Wf22 = (const float*)d_in[12];
    const float* g1   = (const float*)d_in[13];
    const float* b1   = (const float*)d_in[14];
    const float* g2   = (const float*)d_in[15];
    const float* b2   = (const float*)d_in[16];
    const float* g3   = (const float*)d_in[17];
    const float* b3   = (const float*)d_in[18];
    const float* g4   = (const float*)d_in[19];
    const float* b4   = (const float*)d_in[20];
    float* out = (float*)d_out;

    float *q, *k, *v, *o, *x1, *x2, *hbuf;
    cudaGetSymbolAddress((void**)&q,    g_q);
    cudaGetSymbolAddress((void**)&k,    g_k);
    cudaGetSymbolAddress((void**)&v,    g_v);
    cudaGetSymbolAddress((void**)&o,    g_o);
    cudaGetSymbolAddress((void**)&x1,   g_x1);
    cudaGetSymbolAddress((void**)&x2,   g_x2);
    cudaGetSymbolAddress((void**)&hbuf, g_h);

    cudaFuncSetAttribute(attn_mma_kernel,
                         cudaFuncAttributeMaxDynamicSharedMemorySize, ATT_SMEM);

    dim3 agrid(S_ / 128, H_, B_);
    dim3 qkvgrid(D_ / 128, M_ / 128, 3);

    // ---------------- block 1 ----------------
    gemm_qkv_kernel<<<qkvgrid, 256>>>(x, W11, W12, W13, q, k, v);
    attn_mma_kernel<<<agrid, 128, ATT_SMEM>>>(q, k, v, o);
    run_gemm(o, W14, x, x1, D_, D_, 0);
    ln_kernel<<<M_, 256>>>(x1, g1, b1, x2);
    run_gemm(x2, Wf11, nullptr, hbuf, D_, DFF_, 0);
    run_gemm(hbuf, Wf21, x2, x1, DFF_, D_, 0);
    ln_kernel<<<M_, 256>>>(x1, g2, b2, x2);

    // ---------------- block 2 ----------------
    gemm_qkv_kernel<<<qkvgrid, 256>>>(x2, W21, W22, W23, q, k, v);
    attn_mma_kernel<<<agrid, 128, ATT_SMEM>>>(q, k, v, o);
    run_gemm(o, W24, x2, x1, D_, D_, 0);
    ln_kernel<<<M_, 256>>>(x1, g3, b3, x2);
    run_gemm(x2, Wf12, nullptr, hbuf, D_, DFF_, 0);
    run_gemm(hbuf, Wf22, x2, x1, DFF_, D_, 0);
    ln_kernel<<<M_, 256>>>(x1, g4, b4, out);
}

// round 8
// speedup vs baseline: 3.0402x; 1.0358x over previous
#include <cuda_runtime.h>
#include <math.h>

#define B_    4
#define S_    2048
#define D_    256
#define H_    8
#define DK_   32
#define DFF_  1024
#define M_    (B_*S_)      // 8192
#define LNEPS 1e-5f

// ---------------- scratch (static device globals — allowed) ----------------
__device__ float g_q [M_*D_];
__device__ float g_k [M_*D_];
__device__ float g_v [M_*D_];
__device__ float g_o [M_*D_];
__device__ float g_x1[M_*D_];
__device__ float g_x2[M_*D_];
__device__ float g_h [M_*DFF_];

// ---------------- warp reduce helpers ----------------
__device__ __forceinline__ float warp_sum(float v) {
#pragma unroll
    for (int s = 16; s; s >>= 1) v += __shfl_xor_sync(0xffffffffu, v, s);
    return v;
}

// ---------------- PTX helpers (baseline sm_100-safe) ----------------
__device__ __forceinline__ unsigned smem_u32(const void* p) {
    unsigned a;
    asm("{ .reg .u64 t; cvta.to.shared.u64 t, %1; cvt.u32.u64 %0, t; }"
        : "=r"(a) : "l"(p));
    return a;
}
__device__ __forceinline__ void cp16(unsigned dst, const void* src) {
    asm volatile("cp.async.cg.shared.global [%0], [%1], 16;" :: "r"(dst), "l"(src));
}
__device__ __forceinline__ unsigned f2tf32(float f) {
    unsigned r;
    asm("cvt.rna.tf32.f32 %0, %1;" : "=r"(r) : "f"(f));
    return r;
}
__device__ __forceinline__ void mma_tf32(float& c0, float& c1, float& c2, float& c3,
                                         unsigned a0, unsigned a1, unsigned a2, unsigned a3,
                                         unsigned b0, unsigned b1) {
    asm volatile(
        "mma.sync.aligned.m16n8k8.row.col.f32.tf32.tf32.f32 "
        "{%0,%1,%2,%3}, {%4,%5,%6,%7}, {%8,%9}, {%0,%1,%2,%3};"
        : "+f"(c0), "+f"(c1), "+f"(c2), "+f"(c3)
        : "r"(a0), "r"(a1), "r"(a2), "r"(a3), "r"(b0), "r"(b1));
}

// ============================================================================
// tf32 mma.sync GEMM: C[M,O] = relu(A[M,K] @ W[O,K]^T) (+ R if non-null)
// BM=64, BN=128, BK=16. 128 threads = 4 warps; all warps share A fragments
// (warp tile 64x32). Grid = (O/128, M/64) -> 256+ CTAs for D-output GEMMs.
// rnd != 0: round outputs to tf32 (rna).
// ============================================================================
#define GST 20   // smem row stride in floats (16 data + 4 pad)

__device__ __forceinline__ void gemm_mma_body(
    const float* __restrict__ A, const float* __restrict__ W,
    const float* __restrict__ R, float* __restrict__ C,
    int K, int O, int rnd)
{
    __shared__ __align__(16) float As[2][64][GST];
    __shared__ __align__(16) float Bs[2][128][GST];

    const int tid  = threadIdx.x;
    const int wid  = tid >> 5;
    const int lane = tid & 31;
    const int g    = lane >> 2;
    const int t    = lane & 3;
    const int m0 = blockIdx.y * 64;
    const int o0 = blockIdx.x * 128;
    const int wn = wid * 32;

    const unsigned sa_base = smem_u32(&As[0][0][0]);
    const unsigned sb_base = smem_u32(&Bs[0][0][0]);
    const unsigned a_stage = 64u * GST * 4u;
    const unsigned b_stage = 128u * GST * 4u;

    // A: 256 float4/stage -> 2 per thread; B: 512 float4/stage -> 4 per thread
    const int arow = tid >> 1;            // 0..63
    const int akq0 = (tid & 1) * 2;       // 0 or 2

    float acc[4][4][4];
#pragma unroll
    for (int mi = 0; mi < 4; mi++)
#pragma unroll
        for (int ni = 0; ni < 4; ni++)
#pragma unroll
            for (int r = 0; r < 4; r++) acc[mi][ni][r] = 0.f;

    const int nk = K >> 4;

    // ---- prologue: stage 0 ----
#pragma unroll
    for (int i = 0; i < 2; i++) {
        int kq = akq0 + i;
        cp16(sa_base + (unsigned)(arow * (GST * 4) + kq * 16),
             A + (size_t)(m0 + arow) * K + kq * 4);
    }
#pragma unroll
    for (int it = 0; it < 4; it++) {
        int cid = tid + it * 128;         // 0..511
        int row = cid >> 2;               // 0..127
        int kq  = cid & 3;
        cp16(sb_base + (unsigned)(row * (GST * 4) + kq * 16),
             W + (size_t)(o0 + row) * K + kq * 4);
    }
    asm volatile("cp.async.commit_group;" ::: "memory");

    for (int ki = 0; ki < nk; ki++) {
        const int s = ki & 1;

        if (ki + 1 < nk) {
            const int sn = (ki + 1) & 1;
            const int kt = (ki + 1) << 4;
#pragma unroll
            for (int i = 0; i < 2; i++) {
                int kq = akq0 + i;
                cp16(sa_base + (unsigned)(sn * a_stage + arow * (GST * 4) + kq * 16),
                     A + (size_t)(m0 + arow) * K + kt + kq * 4);
            }
#pragma unroll
            for (int it = 0; it < 4; it++) {
                int cid = tid + it * 128;
                int row = cid >> 2;
                int kq  = cid & 3;
                cp16(sb_base + (unsigned)(sn * b_stage + row * (GST * 4) + kq * 16),
                     W + (size_t)(o0 + row) * K + kt + kq * 4);
            }
            asm volatile("cp.async.commit_group;" ::: "memory");
            asm volatile("cp.async.wait_group 1;" ::: "memory");
        } else {
            asm volatile("cp.async.wait_group 0;" ::: "memory");
        }
        __syncthreads();

#pragma unroll
        for (int ks = 0; ks < 2; ks++) {
            const int k0 = ks * 8;
            unsigned af[4][4], bf[4][2];
#pragma unroll
            for (int mi = 0; mi < 4; mi++) {
                const int r = mi * 16 + g;
                af[mi][0] = f2tf32(As[s][r    ][k0 + t]);
                af[mi][1] = f2tf32(As[s][r + 8][k0 + t]);
                af[mi][2] = f2tf32(As[s][r    ][k0 + t + 4]);
                af[mi][3] = f2tf32(As[s][r + 8][k0 + t + 4]);
            }
#pragma unroll
            for (int ni = 0; ni < 4; ni++) {
                const int r = wn + ni * 8 + g;
                bf[ni][0] = f2tf32(Bs[s][r][k0 + t]);
                bf[ni][1] = f2tf32(Bs[s][r][k0 + t + 4]);
            }
#pragma unroll
            for (int mi = 0; mi < 4; mi++)
#pragma unroll
                for (int ni = 0; ni < 4; ni++)
                    mma_tf32(acc[mi][ni][0], acc[mi][ni][1], acc[mi][ni][2], acc[mi][ni][3],
                             af[mi][0], af[mi][1], af[mi][2], af[mi][3],
                             bf[ni][0], bf[ni][1]);
        }
        __syncthreads();
    }

#pragma unroll
    for (int mi = 0; mi < 4; mi++) {
        const int r0 = m0 + mi * 16 + g;
        const int r1 = r0 + 8;
#pragma unroll
        for (int ni = 0; ni < 4; ni++) {
            const int cb = o0 + wn + ni * 8 + 2 * t;
            float v0 = fmaxf(acc[mi][ni][0], 0.f);
            float v1 = fmaxf(acc[mi][ni][1], 0.f);
            float v2 = fmaxf(acc[mi][ni][2], 0.f);
            float v3 = fmaxf(acc[mi][ni][3], 0.f);
            if (R) {
                float2 ra = *(const float2*)&R[(size_t)r0 * O + cb];
                float2 rb = *(const float2*)&R[(size_t)r1 * O + cb];
                v0 += ra.x; v1 += ra.y; v2 += rb.x; v3 += rb.y;
            }
            if (rnd) {
                v0 = __uint_as_float(f2tf32(v0));
                v1 = __uint_as_float(f2tf32(v1));
                v2 = __uint_as_float(f2tf32(v2));
                v3 = __uint_as_float(f2tf32(v3));
            }
            *(float2*)&C[(size_t)r0 * O + cb] = make_float2(v0, v1);
            *(float2*)&C[(size_t)r1 * O + cb] = make_float2(v2, v3);
        }
    }
}

__global__ void __launch_bounds__(128) gemm_mma_kernel(
    const float* __restrict__ A, const float* __restrict__ W,
    const float* __restrict__ R, float* __restrict__ C,
    int K, int O, int rnd)
{
    gemm_mma_body(A, W, R, C, K, O, rnd);
}

// Batched QKV projection: blockIdx.z selects (W, C) pair. rnd=1.
__global__ void __launch_bounds__(128) gemm_qkv_kernel(
    const float* __restrict__ A,
    const float* __restrict__ Wq, const float* __restrict__ Wk, const float* __restrict__ Wv,
    float* __restrict__ Cq, float* __restrict__ Ck, float* __restrict__ Cv)
{
    const float* W = (blockIdx.z == 0) ? Wq : (blockIdx.z == 1) ? Wk : Wv;
    float*       C = (blockIdx.z == 0) ? Cq : (blockIdx.z == 1) ? Ck : Cv;
    gemm_mma_body(A, W, nullptr, C, D_, D_, 1);
}

// ============================================================================
// Flash attention, tf32 mma.sync, 2 row-blocks per warp (32 q rows/warp).
// CTA = 128 thr (4 warps) = 128 q rows. KV tiles of 64, double-buffered.
// ============================================================================
#define AKST 36   // K smem row stride (floats)
#define AVST 40   // V smem row stride
#define ATT_SMEM (2*64*AKST*4 + 2*64*AVST*4)   // 38912 B

__global__ void __launch_bounds__(128, 3) attn_mma_kernel(
    const float* __restrict__ Q, const float* __restrict__ Kb,
    const float* __restrict__ Vb, float* __restrict__ Ob)
{
    extern __shared__ __align__(16) float dsm[];
    float* ks_ = dsm;                  // [2][64][AKST]
    float* vs_ = dsm + 2 * 64 * AKST;  // [2][64][AVST]

    const int tid  = threadIdx.x;
    const int lane = tid & 31;
    const int warp = tid >> 5;
    const int g = lane >> 2;
    const int t = lane & 3;
    const int b = blockIdx.z, h = blockIdx.y;
    const int q0 = blockIdx.x * 128;
    const int r0 = warp * 32;
    const float scale = 0.17677669529663687f;   // 1/sqrt(32)

    // ---- Q fragments (2 row blocks) straight from gmem, pre-rounded tf32 ----
    unsigned qf[2][4][4];
#pragma unroll
    for (int rb = 0; rb < 2; rb++) {
        const float* qrow0 = Q + (size_t)(b * S_ + q0 + r0 + rb * 16 + g    ) * D_ + h * DK_;
        const float* qrow1 = Q + (size_t)(b * S_ + q0 + r0 + rb * 16 + g + 8) * D_ + h * DK_;
#pragma unroll
        for (int kt = 0; kt < 4; kt++) {
            qf[rb][kt][0] = f2tf32(qrow0[kt * 8 + t    ] * scale);
            qf[rb][kt][1] = f2tf32(qrow1[kt * 8 + t    ] * scale);
            qf[rb][kt][2] = f2tf32(qrow0[kt * 8 + t + 4] * scale);
            qf[rb][kt][3] = f2tf32(qrow1[kt * 8 + t + 4] * scale);
        }
    }

    // ---- KV tile loader (cp.async) ----
    const int krow = tid >> 1;
    const int ch0  = (tid & 1) * 4;

    {   // prologue: tile 0 -> buffer 0
        const float* kg = Kb + (size_t)(b * S_ + krow) * D_ + h * DK_;
        const float* vg = Vb + (size_t)(b * S_ + krow) * D_ + h * DK_;
#pragma unroll
        for (int i = 0; i < 4; i++) {
            int ch = ch0 + i;
            cp16(smem_u32(ks_ + (size_t)krow * AKST + ch * 4), kg + ch * 4);
            cp16(smem_u32(vs_ + (size_t)krow * AVST + ch * 4), vg + ch * 4);
        }
        asm volatile("cp.async.commit_group;" ::: "memory");
    }

    float m_[2][2], l_[2][2];
    float oa[2][4][4];
#pragma unroll
    for (int rb = 0; rb < 2; rb++) {
        m_[rb][0] = -1e30f; m_[rb][1] = -1e30f;
        l_[rb][0] = 0.f;    l_[rb][1] = 0.f;
#pragma unroll
        for (int ni = 0; ni < 4; ni++)
#pragma unroll
            for (int r = 0; r < 4; r++) oa[rb][ni][r] = 0.f;
    }

    const int ntiles = S_ / 64;
    const int sl0 = 4 * g + (t >> 1);
    const int sl1 = sl0 + 2;
    const bool odd = (t & 1);

    for (int tile = 0; tile < ntiles; tile++) {
        const int s = tile & 1;

        if (tile + 1 < ntiles) {
            const int sn = s ^ 1;
            const float* kg = Kb + (size_t)(b * S_ + (tile + 1) * 64 + krow) * D_ + h * DK_;
            const float* vg = Vb + (size_t)(b * S_ + (tile + 1) * 64 + krow) * D_ + h * DK_;
#pragma unroll
            for (int i = 0; i < 4; i++) {
                int ch = ch0 + i;
                cp16(smem_u32(ks_ + (size_t)(sn * 64 + krow) * AKST + ch * 4), kg + ch * 4);
                cp16(smem_u32(vs_ + (size_t)(sn * 64 + krow) * AVST + ch * 4), vg + ch * 4);
            }
            asm volatile("cp.async.commit_group;" ::: "memory");
            asm volatile("cp.async.wait_group 1;" ::: "memory");
        } else {
            asm volatile("cp.async.wait_group 0;" ::: "memory");
        }
        __syncthreads();

        // ---- scores for both row blocks: each K fragment feeds 2 MMAs ----
        float sc[2][8][4];
#pragma unroll
        for (int rb = 0; rb < 2; rb++)
#pragma unroll
            for (int ni = 0; ni < 8; ni++)
#pragma unroll
                for (int r = 0; r < 4; r++) sc[rb][ni][r] = 0.f;

#pragma unroll
        for (int kt = 0; kt < 4; kt++) {
#pragma unroll
            for (int ni = 0; ni < 8; ni++) {
                unsigned b0 = ((const unsigned*)ks_)[(size_t)(s * 64 + ni * 8 + g) * AKST + kt * 8 + t];
                unsigned b1 = ((const unsigned*)ks_)[(size_t)(s * 64 + ni * 8 + g) * AKST + kt * 8 + t + 4];
                mma_tf32(sc[0][ni][0], sc[0][ni][1], sc[0][ni][2], sc[0][ni][3],
                         qf[0][kt][0], qf[0][kt][1], qf[0][kt][2], qf[0][kt][3], b0, b1);
                mma_tf32(sc[1][ni][0], sc[1][ni][1], sc[1][ni][2], sc[1][ni][3],
                         qf[1][kt][0], qf[1][kt][1], qf[1][kt][2], qf[1][kt][3], b0, b1);
            }
        }

        // ---- online softmax state update per row block ----
        float mn[2][2], e[2][2];
#pragma unroll
        for (int rb = 0; rb < 2; rb++) {
            float mx0 = -1e30f, mx1 = -1e30f;
#pragma unroll
            for (int ni = 0; ni < 8; ni++) {
                mx0 = fmaxf(mx0, fmaxf(sc[rb][ni][0], sc[rb][ni][1]));
                mx1 = fmaxf(mx1, fmaxf(sc[rb][ni][2], sc[rb][ni][3]));
            }
            mx0 = fmaxf(mx0, __shfl_xor_sync(0xffffffffu, mx0, 1));
            mx0 = fmaxf(mx0, __shfl_xor_sync(0xffffffffu, mx0, 2));
            mx1 = fmaxf(mx1, __shfl_xor_sync(0xffffffffu, mx1, 1));
            mx1 = fmaxf(mx1, __shfl_xor_sync(0xffffffffu, mx1, 2));
            mn[rb][0] = fmaxf(m_[rb][0], mx0);
            mn[rb][1] = fmaxf(m_[rb][1], mx1);
            e[rb][0] = __expf(m_[rb][0] - mn[rb][0]);
            e[rb][1] = __expf(m_[rb][1] - mn[rb][1]);
            m_[rb][0] = mn[rb][0]; m_[rb][1] = mn[rb][1];
#pragma unroll
            for (int ni = 0; ni < 4; ni++) {
                oa[rb][ni][0] *= e[rb][0]; oa[rb][ni][1] *= e[rb][0];
                oa[rb][ni][2] *= e[rb][1]; oa[rb][ni][3] *= e[rb][1];
            }
        }

        // ---- exp -> shfl-transpose -> PV (V fragment feeds 2 MMAs) ----
        float rs[2][2] = {{0.f, 0.f}, {0.f, 0.f}};

#pragma unroll
        for (int kk = 0; kk < 8; kk++) {
            unsigned a_[2][4];
#pragma unroll
            for (int rb = 0; rb < 2; rb++) {
                float p00 = __expf(sc[rb][kk][0] - mn[rb][0]);
                float p01 = __expf(sc[rb][kk][1] - mn[rb][0]);
                float p10 = __expf(sc[rb][kk][2] - mn[rb][1]);
                float p11 = __expf(sc[rb][kk][3] - mn[rb][1]);
                rs[rb][0] += p00 + p01;
                rs[rb][1] += p10 + p11;

                unsigned u00 = f2tf32(p00), u01 = f2tf32(p01);
                unsigned u10 = f2tf32(p10), u11 = f2tf32(p11);

                unsigned x00 = __shfl_sync(0xffffffffu, u00, sl0);
                unsigned x01 = __shfl_sync(0xffffffffu, u01, sl0);
                unsigned x10 = __shfl_sync(0xffffffffu, u10, sl0);
                unsigned x11 = __shfl_sync(0xffffffffu, u11, sl0);
                unsigned y00 = __shfl_sync(0xffffffffu, u00, sl1);
                unsigned y01 = __shfl_sync(0xffffffffu, u01, sl1);
                unsigned y10 = __shfl_sync(0xffffffffu, u10, sl1);
                unsigned y11 = __shfl_sync(0xffffffffu, u11, sl1);

                a_[rb][0] = odd ? x01 : x00;
                a_[rb][1] = odd ? x11 : x10;
                a_[rb][2] = odd ? y01 : y00;
                a_[rb][3] = odd ? y11 : y10;
            }

#pragma unroll
            for (int ni = 0; ni < 4; ni++) {
                unsigned b0 = ((const unsigned*)vs_)[(size_t)(s * 64 + kk * 8 + t    ) * AVST + ni * 8 + g];
                unsigned b1 = ((const unsigned*)vs_)[(size_t)(s * 64 + kk * 8 + t + 4) * AVST + ni * 8 + g];
                mma_tf32(oa[0][ni][0], oa[0][ni][1], oa[0][ni][2], oa[0][ni][3],
                         a_[0][0], a_[0][1], a_[0][2], a_[0][3], b0, b1);
                mma_tf32(oa[1][ni][0], oa[1][ni][1], oa[1][ni][2], oa[1][ni][3],
                         a_[1][0], a_[1][1], a_[1][2], a_[1][3], b0, b1);
            }
        }

#pragma unroll
        for (int rb = 0; rb < 2; rb++) {
            float r0s = rs[rb][0], r1s = rs[rb][1];
            r0s += __shfl_xor_sync(0xffffffffu, r0s, 1);
            r0s += __shfl_xor_sync(0xffffffffu, r0s, 2);
            r1s += __shfl_xor_sync(0xffffffffu, r1s, 1);
            r1s += __shfl_xor_sync(0xffffffffu, r1s, 2);
            l_[rb][0] = l_[rb][0] * e[rb][0] + r0s;
            l_[rb][1] = l_[rb][1] * e[rb][1] + r1s;
        }

        __syncthreads();
    }

    // ---- write O = acc / l ----
#pragma unroll
    for (int rb = 0; rb < 2; rb++) {
        const float inv0 = 1.f / l_[rb][0];
        const float inv1 = 1.f / l_[rb][1];
#pragma unroll
        for (int ni = 0; ni < 4; ni++) {
            const int cb = h * DK_ + ni * 8 + 2 * t;
            size_t ra = (size_t)(b * S_ + q0 + r0 + rb * 16 + g    ) * D_ + cb;
            size_t rx = (size_t)(b * S_ + q0 + r0 + rb * 16 + g + 8) * D_ + cb;
            *(float2*)&Ob[ra] = make_float2(oa[rb][ni][0] * inv0, oa[rb][ni][1] * inv0);
            *(float2*)&Ob[rx] = make_float2(oa[rb][ni][2] * inv1, oa[rb][ni][3] * inv1);
        }
    }
}

// ============================================================================
// LayerNorm over last dim (256). One-pass (sum + sumsq). One CTA per row.
// ============================================================================
__global__ void __launch_bounds__(256) ln_kernel(
    const float* __restrict__ X, const float* __restrict__ g,
    const float* __restrict__ b, float* __restrict__ Y)
{
    __shared__ float red[8], red2[8];
    const int row = blockIdx.x;
    const int tid = threadIdx.x;
    const int lane = tid & 31, warp = tid >> 5;

    float v = X[(size_t)row * D_ + tid];
    float s  = warp_sum(v);
    float s2 = warp_sum(v * v);
    if (!lane) { red[warp] = s; red2[warp] = s2; }
    __syncthreads();
    if (tid < 32) {
        float a = (tid < 8) ? red[tid]  : 0.f;
        float c = (tid < 8) ? red2[tid] : 0.f;
        a = warp_sum(a);
        c = warp_sum(c);
        if (!tid) { red[0] = a; red2[0] = c; }
    }
    __syncthreads();
    float mu  = red[0]  * (1.f / D_);
    float var = red2[0] * (1.f / D_) - mu * mu;
    Y[(size_t)row * D_ + tid] = (v - mu) * rsqrtf(var + LNEPS) * g[tid] + b[tid];
}

// ============================================================================
// host
// ============================================================================
static void run_gemm(const float* A, const float* W, const float* R, float* C,
                     int K, int O, int rnd)
{
    dim3 grid(O / 128, M_ / 64);
    gemm_mma_kernel<<<grid, 128>>>(A, W, R, C, K, O, rnd);
}

extern "C" void kernel_launch(void* const* d_in, const int* in_sizes, int n_in,
                              void* d_out, int out_size)
{
    const float* x    = (const float*)d_in[0];
    const float* W11  = (const float*)d_in[1];
    const float* W12  = (const float*)d_in[2];
    const float* W13  = (const float*)d_in[3];
    const float* W14  = (const float*)d_in[4];
    const float* W21  = (const float*)d_in[5];
    const float* W22  = (const float*)d_in[6];
    const float* W23  = (const float*)d_in[7];
    const float* W24  = (const float*)d_in[8];
    const float* Wf11 = (const float*)d_in[9];
    const float* Wf21 = (const float*)d_in[10];
    const float* Wf12 = (const float*)d_in[11];
    const float* Wf22 = (const float*)d_in[12];
    const float* g1   = (const float*)d_in[13];
    const float* b1   = (const float*)d_in[14];
    const float* g2   = (const float*)d_in[15];
    const float* b2   = (const float*)d_in[16];
    const float* g3   = (const float*)d_in[17];
    const float* b3   = (const float*)d_in[18];
    const float* g4   = (const float*)d_in[19];
    const float* b4   = (const float*)d_in[20];
    float* out = (float*)d_out;

    float *q, *k, *v, *o, *x1, *x2, *hbuf;
    cudaGetSymbolAddress((void**)&q,    g_q);
    cudaGetSymbolAddress((void**)&k,    g_k);
    cudaGetSymbolAddress((void**)&v,    g_v);
    cudaGetSymbolAddress((void**)&o,    g_o);
    cudaGetSymbolAddress((void**)&x1,   g_x1);
    cudaGetSymbolAddress((void**)&x2,   g_x2);
    cudaGetSymbolAddress((void**)&hbuf, g_h);

    cudaFuncSetAttribute(attn_mma_kernel,
                         cudaFuncAttributeMaxDynamicSharedMemorySize, ATT_SMEM);

    dim3 agrid(S_ / 128, H_, B_);
    dim3 qkvgrid(D_ / 128, M_ / 64, 3);

    // ---------------- block 1 ----------------
    gemm_qkv_kernel<<<qkvgrid, 128>>>(x, W11, W12, W13, q, k, v);
    attn_mma_kernel<<<agrid, 128, ATT_SMEM>>>(q, k, v, o);
    run_gemm(o, W14, x, x1, D_, D_, 0);
    ln_kernel<<<M_, 256>>>(x1, g1, b1, x2);
    run_gemm(x2, Wf11, nullptr, hbuf, D_, DFF_, 0);
    run_gemm(hbuf, Wf21, x2, x1, DFF_, D_, 0);
    ln_kernel<<<M_, 256>>>(x1, g2, b2, x2);

    // ---------------- block 2 ----------------
    gemm_qkv_kernel<<<qkvgrid, 128>>>(x2, W21, W22, W23, q, k, v);
    attn_mma_kernel<<<agrid, 128, ATT_SMEM>>>(q, k, v, o);
    run_gemm(o, W24, x2, x1, D_, D_, 0);
    ln_kernel<<<M_, 256>>>(x1, g3, b3, x2);
    run_gemm(x2, Wf12, nullptr, hbuf, D_, DFF_, 0);
    run_gemm(hbuf, Wf22, x2, x1, DFF_, D_, 0);
    ln_kernel<<<M_, 256>>>(x1, g4, b4, out);
}

// round 9
// speedup vs baseline: 4.3119x; 1.4183x over previous
#include <cuda_runtime.h>
#include <cuda_bf16.h>
#include <math.h>

#define B_    4
#define S_    2048
#define D_    256
#define H_    8
#define DK_   32
#define DFF_  1024
#define M_    (B_*S_)      // 8192
#define LNEPS 1e-5f

// ---------------- scratch (static device globals — allowed) ----------------
__device__ __nv_bfloat16 g_q [M_*D_];
__device__ __nv_bfloat16 g_k [M_*D_];
__device__ __nv_bfloat16 g_v [M_*D_];
__device__ float g_o [M_*D_];
__device__ float g_x1[M_*D_];
__device__ float g_x2[M_*D_];
__device__ float g_h [M_*DFF_];

// ---------------- warp reduce helpers ----------------
__device__ __forceinline__ float warp_sum(float v) {
#pragma unroll
    for (int s = 16; s; s >>= 1) v += __shfl_xor_sync(0xffffffffu, v, s);
    return v;
}

// ---------------- PTX helpers (baseline sm_100-safe) ----------------
__device__ __forceinline__ unsigned smem_u32(const void* p) {
    unsigned a;
    asm("{ .reg .u64 t; cvta.to.shared.u64 t, %1; cvt.u32.u64 %0, t; }"
        : "=r"(a) : "l"(p));
    return a;
}
__device__ __forceinline__ void cp16(unsigned dst, const void* src) {
    asm volatile("cp.async.cg.shared.global [%0], [%1], 16;" :: "r"(dst), "l"(src));
}
__device__ __forceinline__ unsigned f2tf32(float f) {
    unsigned r;
    asm("cvt.rna.tf32.f32 %0, %1;" : "=r"(r) : "f"(f));
    return r;
}
__device__ __forceinline__ unsigned pack_bf16(float lo, float hi) {
    unsigned d;
    asm("cvt.rn.bf16x2.f32 %0, %1, %2;" : "=r"(d) : "f"(hi), "f"(lo));
    return d;
}
__device__ __forceinline__ void mma_tf32(float& c0, float& c1, float& c2, float& c3,
                                         unsigned a0, unsigned a1, unsigned a2, unsigned a3,
                                         unsigned b0, unsigned b1) {
    asm volatile(
        "mma.sync.aligned.m16n8k8.row.col.f32.tf32.tf32.f32 "
        "{%0,%1,%2,%3}, {%4,%5,%6,%7}, {%8,%9}, {%0,%1,%2,%3};"
        : "+f"(c0), "+f"(c1), "+f"(c2), "+f"(c3)
        : "r"(a0), "r"(a1), "r"(a2), "r"(a3), "r"(b0), "r"(b1));
}
__device__ __forceinline__ void mma_bf16(float& c0, float& c1, float& c2, float& c3,
                                         unsigned a0, unsigned a1, unsigned a2, unsigned a3,
                                         unsigned b0, unsigned b1) {
    asm volatile(
        "mma.sync.aligned.m16n8k16.row.col.f32.bf16.bf16.f32 "
        "{%0,%1,%2,%3}, {%4,%5,%6,%7}, {%8,%9}, {%0,%1,%2,%3};"
        : "+f"(c0), "+f"(c1), "+f"(c2), "+f"(c3)
        : "r"(a0), "r"(a1), "r"(a2), "r"(a3), "r"(b0), "r"(b1));
}
__device__ __forceinline__ void ldsm_x4(unsigned* r, unsigned addr) {
    asm volatile("ldmatrix.sync.aligned.m8n8.x4.shared.b16 {%0,%1,%2,%3}, [%4];"
                 : "=r"(r[0]), "=r"(r[1]), "=r"(r[2]), "=r"(r[3]) : "r"(addr));
}
__device__ __forceinline__ void ldsm_x4_t(unsigned* r, unsigned addr) {
    asm volatile("ldmatrix.sync.aligned.m8n8.x4.trans.shared.b16 {%0,%1,%2,%3}, [%4];"
                 : "=r"(r[0]), "=r"(r[1]), "=r"(r[2]), "=r"(r[3]) : "r"(addr));
}

// ============================================================================
// tf32 mma.sync GEMM: BM=64, BN=128, BK=16. 128 threads = 4 warps.
// Cb != null -> write bf16 output relu(acc)*scale (QKV path).
// else       -> write fp32 relu(acc) (+R).
// ============================================================================
#define GST 20   // smem row stride in floats (16 data + 4 pad)

__device__ __forceinline__ void gemm_mma_body(
    const float* __restrict__ A, const float* __restrict__ W,
    const float* __restrict__ R, float* __restrict__ C,
    __nv_bfloat16* __restrict__ Cb, float scale,
    int K, int O)
{
    __shared__ __align__(16) float As[2][64][GST];
    __shared__ __align__(16) float Bs[2][128][GST];

    const int tid  = threadIdx.x;
    const int wid  = tid >> 5;
    const int lane = tid & 31;
    const int g    = lane >> 2;
    const int t    = lane & 3;
    const int m0 = blockIdx.y * 64;
    const int o0 = blockIdx.x * 128;
    const int wn = wid * 32;

    const unsigned sa_base = smem_u32(&As[0][0][0]);
    const unsigned sb_base = smem_u32(&Bs[0][0][0]);
    const unsigned a_stage = 64u * GST * 4u;
    const unsigned b_stage = 128u * GST * 4u;

    const int arow = tid >> 1;
    const int akq0 = (tid & 1) * 2;

    float acc[4][4][4];
#pragma unroll
    for (int mi = 0; mi < 4; mi++)
#pragma unroll
        for (int ni = 0; ni < 4; ni++)
#pragma unroll
            for (int r = 0; r < 4; r++) acc[mi][ni][r] = 0.f;

    const int nk = K >> 4;

#pragma unroll
    for (int i = 0; i < 2; i++) {
        int kq = akq0 + i;
        cp16(sa_base + (unsigned)(arow * (GST * 4) + kq * 16),
             A + (size_t)(m0 + arow) * K + kq * 4);
    }
#pragma unroll
    for (int it = 0; it < 4; it++) {
        int cid = tid + it * 128;
        int row = cid >> 2;
        int kq  = cid & 3;
        cp16(sb_base + (unsigned)(row * (GST * 4) + kq * 16),
             W + (size_t)(o0 + row) * K + kq * 4);
    }
    asm volatile("cp.async.commit_group;" ::: "memory");

    for (int ki = 0; ki < nk; ki++) {
        const int s = ki & 1;

        if (ki + 1 < nk) {
            const int sn = (ki + 1) & 1;
            const int kt = (ki + 1) << 4;
#pragma unroll
            for (int i = 0; i < 2; i++) {
                int kq = akq0 + i;
                cp16(sa_base + (unsigned)(sn * a_stage + arow * (GST * 4) + kq * 16),
                     A + (size_t)(m0 + arow) * K + kt + kq * 4);
            }
#pragma unroll
            for (int it = 0; it < 4; it++) {
                int cid = tid + it * 128;
                int row = cid >> 2;
                int kq  = cid & 3;
                cp16(sb_base + (unsigned)(sn * b_stage + row * (GST * 4) + kq * 16),
                     W + (size_t)(o0 + row) * K + kt + kq * 4);
            }
            asm volatile("cp.async.commit_group;" ::: "memory");
            asm volatile("cp.async.wait_group 1;" ::: "memory");
        } else {
            asm volatile("cp.async.wait_group 0;" ::: "memory");
        }
        __syncthreads();

#pragma unroll
        for (int ks = 0; ks < 2; ks++) {
            const int k0 = ks * 8;
            unsigned af[4][4], bf[4][2];
#pragma unroll
            for (int mi = 0; mi < 4; mi++) {
                const int r = mi * 16 + g;
                af[mi][0] = f2tf32(As[s][r    ][k0 + t]);
                af[mi][1] = f2tf32(As[s][r + 8][k0 + t]);
                af[mi][2] = f2tf32(As[s][r    ][k0 + t + 4]);
                af[mi][3] = f2tf32(As[s][r + 8][k0 + t + 4]);
            }
#pragma unroll
            for (int ni = 0; ni < 4; ni++) {
                const int r = wn + ni * 8 + g;
                bf[ni][0] = f2tf32(Bs[s][r][k0 + t]);
                bf[ni][1] = f2tf32(Bs[s][r][k0 + t + 4]);
            }
#pragma unroll
            for (int mi = 0; mi < 4; mi++)
#pragma unroll
                for (int ni = 0; ni < 4; ni++)
                    mma_tf32(acc[mi][ni][0], acc[mi][ni][1], acc[mi][ni][2], acc[mi][ni][3],
                             af[mi][0], af[mi][1], af[mi][2], af[mi][3],
                             bf[ni][0], bf[ni][1]);
        }
        __syncthreads();
    }

#pragma unroll
    for (int mi = 0; mi < 4; mi++) {
        const int r0 = m0 + mi * 16 + g;
        const int r1 = r0 + 8;
#pragma unroll
        for (int ni = 0; ni < 4; ni++) {
            const int cb = o0 + wn + ni * 8 + 2 * t;
            float v0 = fmaxf(acc[mi][ni][0], 0.f);
            float v1 = fmaxf(acc[mi][ni][1], 0.f);
            float v2 = fmaxf(acc[mi][ni][2], 0.f);
            float v3 = fmaxf(acc[mi][ni][3], 0.f);
            if (Cb) {
                v0 *= scale; v1 *= scale; v2 *= scale; v3 *= scale;
                *(unsigned*)&Cb[(size_t)r0 * O + cb] = pack_bf16(v0, v1);
                *(unsigned*)&Cb[(size_t)r1 * O + cb] = pack_bf16(v2, v3);
            } else {
                if (R) {
                    float2 ra = *(const float2*)&R[(size_t)r0 * O + cb];
                    float2 rb = *(const float2*)&R[(size_t)r1 * O + cb];
                    v0 += ra.x; v1 += ra.y; v2 += rb.x; v3 += rb.y;
                }
                *(float2*)&C[(size_t)r0 * O + cb] = make_float2(v0, v1);
                *(float2*)&C[(size_t)r1 * O + cb] = make_float2(v2, v3);
            }
        }
    }
}

__global__ void __launch_bounds__(128) gemm_mma_kernel(
    const float* __restrict__ A, const float* __restrict__ W,
    const float* __restrict__ R, float* __restrict__ C,
    int K, int O)
{
    gemm_mma_body(A, W, R, C, nullptr, 1.f, K, O);
}

// Batched QKV projection -> bf16 outputs; Q pre-scaled by 1/sqrt(dk).
__global__ void __launch_bounds__(128) gemm_qkv_kernel(
    const float* __restrict__ A,
    const float* __restrict__ Wq, const float* __restrict__ Wk, const float* __restrict__ Wv,
    __nv_bfloat16* __restrict__ Cq, __nv_bfloat16* __restrict__ Ck, __nv_bfloat16* __restrict__ Cv)
{
    const float* W = (blockIdx.z == 0) ? Wq : (blockIdx.z == 1) ? Wk : Wv;
    __nv_bfloat16* C = (blockIdx.z == 0) ? Cq : (blockIdx.z == 1) ? Ck : Cv;
    const float scale = (blockIdx.z == 0) ? 0.17677669529663687f : 1.f;
    gemm_mma_body(A, W, nullptr, nullptr, C, scale, D_, D_);
}

// ============================================================================
// Flash attention, bf16 m16n8k16 mma. 2 row-blocks/warp (32 q rows/warp),
// CTA = 128 thr = 128 q rows. KV tiles of 64 keys, double-buffered cp.async.
// Score C-frag feeds PV A-frag directly (no transpose). K frags via ldmatrix,
// V^T frags via ldmatrix.trans. Row stride 40 bf16 (80B) = conflict-free.
// ============================================================================
#define AKVST 40   // K/V smem row stride in bf16 elements (80 bytes)
#define ATT_SMEM (2 * 2 * 64 * AKVST * 2)   // 20480 B

__global__ void __launch_bounds__(128, 3) attn_mma_kernel(
    const __nv_bfloat16* __restrict__ Q, const __nv_bfloat16* __restrict__ Kb,
    const __nv_bfloat16* __restrict__ Vb, float* __restrict__ Ob)
{
    extern __shared__ __align__(16) char dsm[];
    const unsigned ksb = smem_u32(dsm);                      // [2][64][AKVST] bf16
    const unsigned vsb = ksb + 2u * 64u * AKVST * 2u;        // [2][64][AKVST] bf16

    const int tid  = threadIdx.x;
    const int lane = tid & 31;
    const int warp = tid >> 5;
    const int g = lane >> 2;
    const int t = lane & 3;
    const int b = blockIdx.z, h = blockIdx.y;
    const int q0 = blockIdx.x * 128;
    const int r0 = warp * 32;

    // ---- Q fragments (bf16, pre-scaled by producer) ----
    unsigned qf[2][2][4];
#pragma unroll
    for (int rb = 0; rb < 2; rb++) {
        const __nv_bfloat16* q0p = Q + (size_t)(b * S_ + q0 + r0 + rb * 16 + g    ) * D_ + h * DK_;
        const __nv_bfloat16* q1p = Q + (size_t)(b * S_ + q0 + r0 + rb * 16 + g + 8) * D_ + h * DK_;
#pragma unroll
        for (int kt = 0; kt < 2; kt++) {
            qf[rb][kt][0] = *(const unsigned*)(q0p + kt * 16 + 2 * t);
            qf[rb][kt][1] = *(const unsigned*)(q1p + kt * 16 + 2 * t);
            qf[rb][kt][2] = *(const unsigned*)(q0p + kt * 16 + 2 * t + 8);
            qf[rb][kt][3] = *(const unsigned*)(q1p + kt * 16 + 2 * t + 8);
        }
    }

    // ---- KV tile loader: 64 rows x 64B each for K and V ----
    const int krow = tid >> 1;
    const int ch0  = (tid & 1) * 2;

    {   // prologue: tile 0 -> buffer 0
        const __nv_bfloat16* kg = Kb + (size_t)(b * S_ + krow) * D_ + h * DK_;
        const __nv_bfloat16* vg = Vb + (size_t)(b * S_ + krow) * D_ + h * DK_;
#pragma unroll
        for (int i = 0; i < 2; i++) {
            int ch = ch0 + i;
            cp16(ksb + (unsigned)(krow * 80 + ch * 16), kg + ch * 8);
            cp16(vsb + (unsigned)(krow * 80 + ch * 16), vg + ch * 8);
        }
        asm volatile("cp.async.commit_group;" ::: "memory");
    }

    float m_[2][2], l_[2][2];
    float oa[2][4][4];
#pragma unroll
    for (int rb = 0; rb < 2; rb++) {
        m_[rb][0] = -1e30f; m_[rb][1] = -1e30f;
        l_[rb][0] = 0.f;    l_[rb][1] = 0.f;
#pragma unroll
        for (int ni = 0; ni < 4; ni++)
#pragma unroll
            for (int r = 0; r < 4; r++) oa[rb][ni][r] = 0.f;
    }

    const int ntiles = S_ / 64;
    const unsigned stage_b = 64u * 80u;

    // ldmatrix address components (within a stage)
    const unsigned k_lrow = (unsigned)(lane & 7);
    const unsigned k_lcol = (unsigned)(lane >> 3) * 16u;            // K: 4 tiles across dk
    const unsigned v_lrow = (unsigned)((lane & 7) + ((lane >> 3) & 1) * 8);
    const unsigned v_lcol = (unsigned)(lane >> 4) * 16u;            // V: 2x2 tiles

    for (int tile = 0; tile < ntiles; tile++) {
        const int s = tile & 1;
        const unsigned kst = ksb + (unsigned)s * stage_b;
        const unsigned vst = vsb + (unsigned)s * stage_b;

        if (tile + 1 < ntiles) {
            const int sn = s ^ 1;
            const __nv_bfloat16* kg = Kb + (size_t)(b * S_ + (tile + 1) * 64 + krow) * D_ + h * DK_;
            const __nv_bfloat16* vg = Vb + (size_t)(b * S_ + (tile + 1) * 64 + krow) * D_ + h * DK_;
#pragma unroll
            for (int i = 0; i < 2; i++) {
                int ch = ch0 + i;
                cp16(ksb + (unsigned)(sn * stage_b + krow * 80 + ch * 16), kg + ch * 8);
                cp16(vsb + (unsigned)(sn * stage_b + krow * 80 + ch * 16), vg + ch * 8);
            }
            asm volatile("cp.async.commit_group;" ::: "memory");
            asm volatile("cp.async.wait_group 1;" ::: "memory");
        } else {
            asm volatile("cp.async.wait_group 0;" ::: "memory");
        }
        __syncthreads();

        // ---- scores: S = Q K^T  (k16 over dk=32 -> 2 steps) ----
        float sc[2][8][4];
#pragma unroll
        for (int rb = 0; rb < 2; rb++)
#pragma unroll
            for (int ni = 0; ni < 8; ni++)
#pragma unroll
                for (int r = 0; r < 4; r++) sc[rb][ni][r] = 0.f;

#pragma unroll
        for (int ni = 0; ni < 8; ni++) {
            unsigned kb[4];
            ldsm_x4(kb, kst + (unsigned)(ni * 8 + k_lrow) * 80u + k_lcol);
#pragma unroll
            for (int rb = 0; rb < 2; rb++) {
                mma_bf16(sc[rb][ni][0], sc[rb][ni][1], sc[rb][ni][2], sc[rb][ni][3],
                         qf[rb][0][0], qf[rb][0][1], qf[rb][0][2], qf[rb][0][3], kb[0], kb[1]);
                mma_bf16(sc[rb][ni][0], sc[rb][ni][1], sc[rb][ni][2], sc[rb][ni][3],
                         qf[rb][1][0], qf[rb][1][1], qf[rb][1][2], qf[rb][1][3], kb[2], kb[3]);
            }
        }

        // ---- online softmax state update per row block ----
        float mn[2][2], e[2][2];
#pragma unroll
        for (int rb = 0; rb < 2; rb++) {
            float mx0 = -1e30f, mx1 = -1e30f;
#pragma unroll
            for (int ni = 0; ni < 8; ni++) {
                mx0 = fmaxf(mx0, fmaxf(sc[rb][ni][0], sc[rb][ni][1]));
                mx1 = fmaxf(mx1, fmaxf(sc[rb][ni][2], sc[rb][ni][3]));
            }
            mx0 = fmaxf(mx0, __shfl_xor_sync(0xffffffffu, mx0, 1));
            mx0 = fmaxf(mx0, __shfl_xor_sync(0xffffffffu, mx0, 2));
            mx1 = fmaxf(mx1, __shfl_xor_sync(0xffffffffu, mx1, 1));
            mx1 = fmaxf(mx1, __shfl_xor_sync(0xffffffffu, mx1, 2));
            mn[rb][0] = fmaxf(m_[rb][0], mx0);
            mn[rb][1] = fmaxf(m_[rb][1], mx1);
            e[rb][0] = __expf(m_[rb][0] - mn[rb][0]);
            e[rb][1] = __expf(m_[rb][1] - mn[rb][1]);
            m_[rb][0] = mn[rb][0]; m_[rb][1] = mn[rb][1];
#pragma unroll
            for (int ni = 0; ni < 4; ni++) {
                oa[rb][ni][0] *= e[rb][0]; oa[rb][ni][1] *= e[rb][0];
                oa[rb][ni][2] *= e[rb][1]; oa[rb][ni][3] *= e[rb][1];
            }
        }

        // ---- PV: exp -> pack (C-frag == A-frag layout, no transpose) ----
        float rs[2][2] = {{0.f, 0.f}, {0.f, 0.f}};

#pragma unroll
        for (int kk = 0; kk < 4; kk++) {
            unsigned v0[4], v1[4];
            const unsigned vrow = vst + (unsigned)(kk * 16 + v_lrow) * 80u + v_lcol;
            ldsm_x4_t(v0, vrow);
            ldsm_x4_t(v1, vrow + 32u);
#pragma unroll
            for (int rb = 0; rb < 2; rb++) {
                float e00 = __expf(sc[rb][2*kk  ][0] - mn[rb][0]);
                float e01 = __expf(sc[rb][2*kk  ][1] - mn[rb][0]);
                float e02 = __expf(sc[rb][2*kk  ][2] - mn[rb][1]);
                float e03 = __expf(sc[rb][2*kk  ][3] - mn[rb][1]);
                float f00 = __expf(sc[rb][2*kk+1][0] - mn[rb][0]);
                float f01 = __expf(sc[rb][2*kk+1][1] - mn[rb][0]);
                float f02 = __expf(sc[rb][2*kk+1][2] - mn[rb][1]);
                float f03 = __expf(sc[rb][2*kk+1][3] - mn[rb][1]);
                rs[rb][0] += e00 + e01 + f00 + f01;
                rs[rb][1] += e02 + e03 + f02 + f03;

                unsigned a0 = pack_bf16(e00, e01);
                unsigned a1 = pack_bf16(e02, e03);
                unsigned a2 = pack_bf16(f00, f01);
                unsigned a3 = pack_bf16(f02, f03);

                mma_bf16(oa[rb][0][0], oa[rb][0][1], oa[rb][0][2], oa[rb][0][3],
                         a0, a1, a2, a3, v0[0], v0[1]);
                mma_bf16(oa[rb][1][0], oa[rb][1][1], oa[rb][1][2], oa[rb][1][3],
                         a0, a1, a2, a3, v0[2], v0[3]);
                mma_bf16(oa[rb][2][0], oa[rb][2][1], oa[rb][2][2], oa[rb][2][3],
                         a0, a1, a2, a3, v1[0], v1[1]);
                mma_bf16(oa[rb][3][0], oa[rb][3][1], oa[rb][3][2], oa[rb][3][3],
                         a0, a1, a2, a3, v1[2], v1[3]);
            }
        }

#pragma unroll
        for (int rb = 0; rb < 2; rb++) {
            float r0s = rs[rb][0], r1s = rs[rb][1];
            r0s += __shfl_xor_sync(0xffffffffu, r0s, 1);
            r0s += __shfl_xor_sync(0xffffffffu, r0s, 2);
            r1s += __shfl_xor_sync(0xffffffffu, r1s, 1);
            r1s += __shfl_xor_sync(0xffffffffu, r1s, 2);
            l_[rb][0] = l_[rb][0] * e[rb][0] + r0s;
            l_[rb][1] = l_[rb][1] * e[rb][1] + r1s;
        }

        __syncthreads();
    }

    // ---- write O = acc / l (fp32) ----
#pragma unroll
    for (int rb = 0; rb < 2; rb++) {
        const float inv0 = 1.f / l_[rb][0];
        const float inv1 = 1.f / l_[rb][1];
#pragma unroll
        for (int ni = 0; ni < 4; ni++) {
            const int cb = h * DK_ + ni * 8 + 2 * t;
            size_t ra = (size_t)(b * S_ + q0 + r0 + rb * 16 + g    ) * D_ + cb;
            size_t rx = (size_t)(b * S_ + q0 + r0 + rb * 16 + g + 8) * D_ + cb;
            *(float2*)&Ob[ra] = make_float2(oa[rb][ni][0] * inv0, oa[rb][ni][1] * inv0);
            *(float2*)&Ob[rx] = make_float2(oa[rb][ni][2] * inv1, oa[rb][ni][3] * inv1);
        }
    }
}

// ============================================================================
// LayerNorm over last dim (256). One-pass (sum + sumsq). One CTA per row.
// ============================================================================
__global__ void __launch_bounds__(256) ln_kernel(
    const float* __restrict__ X, const float* __restrict__ g,
    const float* __restrict__ b, float* __restrict__ Y)
{
    __shared__ float red[8], red2[8];
    const int row = blockIdx.x;
    const int tid = threadIdx.x;
    const int lane = tid & 31, warp = tid >> 5;

    float v = X[(size_t)row * D_ + tid];
    float s  = warp_sum(v);
    float s2 = warp_sum(v * v);
    if (!lane) { red[warp] = s; red2[warp] = s2; }
    __syncthreads();
    if (tid < 32) {
        float a = (tid < 8) ? red[tid]  : 0.f;
        float c = (tid < 8) ? red2[tid] : 0.f;
        a = warp_sum(a);
        c = warp_sum(c);
        if (!tid) { red[0] = a; red2[0] = c; }
    }
    __syncthreads();
    float mu  = red[0]  * (1.f / D_);
    float var = red2[0] * (1.f / D_) - mu * mu;
    Y[(size_t)row * D_ + tid] = (v - mu) * rsqrtf(var + LNEPS) * g[tid] + b[tid];
}

// ============================================================================
// host
// ============================================================================
static void run_gemm(const float* A, const float* W, const float* R, float* C,
                     int K, int O)
{
    dim3 grid(O / 128, M_ / 64);
    gemm_mma_kernel<<<grid, 128>>>(A, W, R, C, K, O);
}

extern "C" void kernel_launch(void* const* d_in, const int* in_sizes, int n_in,
                              void* d_out, int out_size)
{
    const float* x    = (const float*)d_in[0];
    const float* W11  = (const float*)d_in[1];
    const float* W12  = (const float*)d_in[2];
    const float* W13  = (const float*)d_in[3];
    const float* W14  = (const float*)d_in[4];
    const float* W21  = (const float*)d_in[5];
    const float* W22  = (const float*)d_in[6];
    const float* W23  = (const float*)d_in[7];
    const float* W24  = (const float*)d_in[8];
    const float* Wf11 = (const float*)d_in[9];
    const float* Wf21 = (const float*)d_in[10];
    const float* Wf12 = (const float*)d_in[11];
    const float* Wf22 = (const float*)d_in[12];
    const float* g1   = (const float*)d_in[13];
    const float* b1   = (const float*)d_in[14];
    const float* g2   = (const float*)d_in[15];
    const float* b2   = (const float*)d_in[16];
    const float* g3   = (const float*)d_in[17];
    const float* b3   = (const float*)d_in[18];
    const float* g4   = (const float*)d_in[19];
    const float* b4   = (const float*)d_in[20];
    float* out = (float*)d_out;

    __nv_bfloat16 *q, *k, *v;
    float *o, *x1, *x2, *hbuf;
    cudaGetSymbolAddress((void**)&q,    g_q);
    cudaGetSymbolAddress((void**)&k,    g_k);
    cudaGetSymbolAddress((void**)&v,    g_v);
    cudaGetSymbolAddress((void**)&o,    g_o);
    cudaGetSymbolAddress((void**)&x1,   g_x1);
    cudaGetSymbolAddress((void**)&x2,   g_x2);
    cudaGetSymbolAddress((void**)&hbuf, g_h);

    cudaFuncSetAttribute(attn_mma_kernel,
                         cudaFuncAttributeMaxDynamicSharedMemorySize, ATT_SMEM);

    dim3 agrid(S_ / 128, H_, B_);
    dim3 qkvgrid(D_ / 128, M_ / 64, 3);

    // ---------------- block 1 ----------------
    gemm_qkv_kernel<<<qkvgrid, 128>>>(x, W11, W12, W13, q, k, v);
    attn_mma_kernel<<<agrid, 128, ATT_SMEM>>>(q, k, v, o);
    run_gemm(o, W14, x, x1, D_, D_);
    ln_kernel<<<M_, 256>>>(x1, g1, b1, x2);
    run_gemm(x2, Wf11, nullptr, hbuf, D_, DFF_);
    run_gemm(hbuf, Wf21, x2, x1, DFF_, D_);
    ln_kernel<<<M_, 256>>>(x1, g2, b2, x2);

    // ---------------- block 2 ----------------
    gemm_qkv_kernel<<<qkvgrid, 128>>>(x2, W21, W22, W23, q, k, v);
    attn_mma_kernel<<<agrid, 128, ATT_SMEM>>>(q, k, v, o);
    run_gemm(o, W24, x2, x1, D_, D_);
    ln_kernel<<<M_, 256>>>(x1, g3, b3, x2);
    run_gemm(x2, Wf12, nullptr, hbuf, D_, DFF_);
    run_gemm(hbuf, Wf22, x2, x1, DFF_, D_);
    ln_kernel<<<M_, 256>>>(x1, g4, b4, out);
}

// round 10
// speedup vs baseline: 5.5648x; 1.2906x over previous
#include <cuda_runtime.h>
#include <cuda_bf16.h>
#include <math.h>

#define B_    4
#define S_    2048
#define D_    256
#define H_    8
#define DK_   32
#define DFF_  1024
#define M_    (B_*S_)      // 8192
#define LNEPS 1e-5f

// ---------------- scratch (static device globals — allowed) ----------------
__device__ __nv_bfloat16 g_q [M_*D_];
__device__ __nv_bfloat16 g_k [M_*D_];
__device__ __nv_bfloat16 g_v [M_*D_];
__device__ __nv_bfloat16 g_o [M_*D_];
__device__ __nv_bfloat16 g_xb [M_*D_];     // bf16 copy of block input
__device__ __nv_bfloat16 g_x2b[M_*D_];     // bf16 copy of LN output
__device__ __nv_bfloat16 g_h [M_*DFF_];    // FFN hidden (bf16)
__device__ __nv_bfloat16 g_wb[1572864];    // all 12 weights in bf16
__device__ float g_x1[M_*D_];
__device__ float g_x2[M_*D_];

// weight element offsets in g_wb
#define WOFF_11   0
#define WOFF_12   65536
#define WOFF_13   131072
#define WOFF_14   196608
#define WOFF_21   262144
#define WOFF_22   327680
#define WOFF_23   393216
#define WOFF_24   458752
#define WOFF_F11  524288
#define WOFF_F21  786432
#define WOFF_F12  1048576
#define WOFF_F22  1310720

// ---------------- warp reduce helpers ----------------
__device__ __forceinline__ float warp_sum(float v) {
#pragma unroll
    for (int s = 16; s; s >>= 1) v += __shfl_xor_sync(0xffffffffu, v, s);
    return v;
}

// ---------------- PTX helpers (baseline sm_100-safe) ----------------
__device__ __forceinline__ unsigned smem_u32(const void* p) {
    unsigned a;
    asm("{ .reg .u64 t; cvta.to.shared.u64 t, %1; cvt.u32.u64 %0, t; }"
        : "=r"(a) : "l"(p));
    return a;
}
__device__ __forceinline__ void cp16(unsigned dst, const void* src) {
    asm volatile("cp.async.cg.shared.global [%0], [%1], 16;" :: "r"(dst), "l"(src));
}
__device__ __forceinline__ unsigned pack_bf16(float lo, float hi) {
    unsigned d;
    asm("cvt.rn.bf16x2.f32 %0, %1, %2;" : "=r"(d) : "f"(hi), "f"(lo));
    return d;
}
__device__ __forceinline__ void mma_bf16(float& c0, float& c1, float& c2, float& c3,
                                         unsigned a0, unsigned a1, unsigned a2, unsigned a3,
                                         unsigned b0, unsigned b1) {
    asm volatile(
        "mma.sync.aligned.m16n8k16.row.col.f32.bf16.bf16.f32 "
        "{%0,%1,%2,%3}, {%4,%5,%6,%7}, {%8,%9}, {%0,%1,%2,%3};"
        : "+f"(c0), "+f"(c1), "+f"(c2), "+f"(c3)
        : "r"(a0), "r"(a1), "r"(a2), "r"(a3), "r"(b0), "r"(b1));
}
__device__ __forceinline__ void ldsm_x4(unsigned* r, unsigned addr) {
    asm volatile("ldmatrix.sync.aligned.m8n8.x4.shared.b16 {%0,%1,%2,%3}, [%4];"
                 : "=r"(r[0]), "=r"(r[1]), "=r"(r[2]), "=r"(r[3]) : "r"(addr));
}
__device__ __forceinline__ void ldsm_x4_t(unsigned* r, unsigned addr) {
    asm volatile("ldmatrix.sync.aligned.m8n8.x4.trans.shared.b16 {%0,%1,%2,%3}, [%4];"
                 : "=r"(r[0]), "=r"(r[1]), "=r"(r[2]), "=r"(r[3]) : "r"(addr));
}

// ============================================================================
// Convert kernel: x (fp32->bf16) + all 12 weights into g_wb. Pair-granular.
// Total pairs = 1835008 = 7168 blocks x 256 threads, 1 pair each.
// ============================================================================
#define XPAIRS  (M_*D_/2)        // 1048576
#define WDPAIRS (D_*D_/2)        // 32768
#define WFPAIRS (DFF_*D_/2)      // 131072

__global__ void __launch_bounds__(256) convert_kernel(
    const float* __restrict__ x,
    const float* __restrict__ W11, const float* __restrict__ W12,
    const float* __restrict__ W13, const float* __restrict__ W14,
    const float* __restrict__ W21, const float* __restrict__ W22,
    const float* __restrict__ W23, const float* __restrict__ W24,
    const float* __restrict__ Wf11, const float* __restrict__ Wf21,
    const float* __restrict__ Wf12, const float* __restrict__ Wf22)
{
    const int idx = blockIdx.x * 256 + threadIdx.x;
    const float* src;
    unsigned* dst;
    int off;
    if (idx < XPAIRS) {
        src = x; dst = (unsigned*)g_xb; off = idx;
    } else {
        int r = idx - XPAIRS;
        if (r < 8 * WDPAIRS) {
            int w = r / WDPAIRS;
            src = (w == 0) ? W11 : (w == 1) ? W12 : (w == 2) ? W13 : (w == 3) ? W14 :
                  (w == 4) ? W21 : (w == 5) ? W22 : (w == 6) ? W23 : W24;
            dst = (unsigned*)g_wb + w * WDPAIRS;
            off = r - w * WDPAIRS;
        } else {
            int r2 = r - 8 * WDPAIRS;
            int w = r2 / WFPAIRS;
            src = (w == 0) ? Wf11 : (w == 1) ? Wf21 : (w == 2) ? Wf12 : Wf22;
            dst = (unsigned*)g_wb + 8 * WDPAIRS + w * WFPAIRS;
            off = r2 - w * WFPAIRS;
        }
    }
    float2 v = ((const float2*)src)[off];
    dst[off] = pack_bf16(v.x, v.y);
}

// ============================================================================
// bf16 mma.sync GEMM: BM=64, BN=128, BK=32. 128 threads = 4 warps.
// A [M][K], W [O][K], both bf16 row-major. ldmatrix fragment loads,
// smem row stride 40 bf16 (80B, conflict-free for ldmatrix).
// Cb != null -> bf16 out relu(acc)*scale; else fp32 out relu(acc) (+R).
// ============================================================================
#define BST 40   // smem row stride in bf16 elements

__device__ __forceinline__ void gemm_bf16_body(
    const __nv_bfloat16* __restrict__ A, const __nv_bfloat16* __restrict__ W,
    const float* __restrict__ R, float* __restrict__ C,
    __nv_bfloat16* __restrict__ Cb, float scale,
    int K, int O)
{
    __shared__ __align__(16) __nv_bfloat16 As[2][64][BST];
    __shared__ __align__(16) __nv_bfloat16 Bs[2][128][BST];

    const int tid  = threadIdx.x;
    const int wid  = tid >> 5;
    const int lane = tid & 31;
    const int g    = lane >> 2;
    const int t    = lane & 3;
    const int m0 = blockIdx.y * 64;
    const int o0 = blockIdx.x * 128;
    const int wn = wid * 32;

    const int arow = tid >> 1;
    const int ach0 = (tid & 1) * 2;

    float acc[4][4][4];
#pragma unroll
    for (int mi = 0; mi < 4; mi++)
#pragma unroll
        for (int ni = 0; ni < 4; ni++)
#pragma unroll
            for (int r = 0; r < 4; r++) acc[mi][ni][r] = 0.f;

    const int nk = K >> 5;

    // ---- prologue: stage 0 ----
#pragma unroll
    for (int i = 0; i < 2; i++) {
        int ch = ach0 + i;
        cp16(smem_u32(&As[0][arow][0]) + (unsigned)(ch * 16),
             A + (size_t)(m0 + arow) * K + ch * 8);
    }
#pragma unroll
    for (int it = 0; it < 4; it++) {
        int cid = tid + it * 128;
        int row = cid >> 2;
        int ch  = cid & 3;
        cp16(smem_u32(&Bs[0][row][0]) + (unsigned)(ch * 16),
             W + (size_t)(o0 + row) * K + ch * 8);
    }
    asm volatile("cp.async.commit_group;" ::: "memory");

    for (int ki = 0; ki < nk; ki++) {
        const int s = ki & 1;

        if (ki + 1 < nk) {
            const int sn = (ki + 1) & 1;
            const int kt = (ki + 1) << 5;
#pragma unroll
            for (int i = 0; i < 2; i++) {
                int ch = ach0 + i;
                cp16(smem_u32(&As[sn][arow][0]) + (unsigned)(ch * 16),
                     A + (size_t)(m0 + arow) * K + kt + ch * 8);
            }
#pragma unroll
            for (int it = 0; it < 4; it++) {
                int cid = tid + it * 128;
                int row = cid >> 2;
                int ch  = cid & 3;
                cp16(smem_u32(&Bs[sn][row][0]) + (unsigned)(ch * 16),
                     W + (size_t)(o0 + row) * K + kt + ch * 8);
            }
            asm volatile("cp.async.commit_group;" ::: "memory");
            asm volatile("cp.async.wait_group 1;" ::: "memory");
        } else {
            asm volatile("cp.async.wait_group 0;" ::: "memory");
        }
        __syncthreads();

        // ---- fragments via ldmatrix ----
        unsigned af[4][2][4];   // [mi][ks][reg]
#pragma unroll
        for (int mi = 0; mi < 4; mi++)
#pragma unroll
            for (int ks = 0; ks < 2; ks++)
                ldsm_x4(af[mi][ks],
                        smem_u32(&As[s][mi * 16 + (lane & 15)][0]) +
                        (unsigned)(ks * 32 + (lane >> 4) * 16));

        unsigned bfr[4][4];     // [ni][reg] covers n8 x k32
#pragma unroll
        for (int ni = 0; ni < 4; ni++)
            ldsm_x4(bfr[ni],
                    smem_u32(&Bs[s][wn + ni * 8 + (lane & 7)][0]) +
                    (unsigned)((lane >> 3) * 16));

#pragma unroll
        for (int mi = 0; mi < 4; mi++)
#pragma unroll
            for (int ni = 0; ni < 4; ni++) {
                mma_bf16(acc[mi][ni][0], acc[mi][ni][1], acc[mi][ni][2], acc[mi][ni][3],
                         af[mi][0][0], af[mi][0][1], af[mi][0][2], af[mi][0][3],
                         bfr[ni][0], bfr[ni][1]);
                mma_bf16(acc[mi][ni][0], acc[mi][ni][1], acc[mi][ni][2], acc[mi][ni][3],
                         af[mi][1][0], af[mi][1][1], af[mi][1][2], af[mi][1][3],
                         bfr[ni][2], bfr[ni][3]);
            }
        __syncthreads();
    }

    // ---- epilogue ----
#pragma unroll
    for (int mi = 0; mi < 4; mi++) {
        const int r0 = m0 + mi * 16 + g;
        const int r1 = r0 + 8;
#pragma unroll
        for (int ni = 0; ni < 4; ni++) {
            const int cb = o0 + wn + ni * 8 + 2 * t;
            float v0 = fmaxf(acc[mi][ni][0], 0.f);
            float v1 = fmaxf(acc[mi][ni][1], 0.f);
            float v2 = fmaxf(acc[mi][ni][2], 0.f);
            float v3 = fmaxf(acc[mi][ni][3], 0.f);
            if (Cb) {
                v0 *= scale; v1 *= scale; v2 *= scale; v3 *= scale;
                *(unsigned*)&Cb[(size_t)r0 * O + cb] = pack_bf16(v0, v1);
                *(unsigned*)&Cb[(size_t)r1 * O + cb] = pack_bf16(v2, v3);
            } else {
                if (R) {
                    float2 ra = *(const float2*)&R[(size_t)r0 * O + cb];
                    float2 rb = *(const float2*)&R[(size_t)r1 * O + cb];
                    v0 += ra.x; v1 += ra.y; v2 += rb.x; v3 += rb.y;
                }
                *(float2*)&C[(size_t)r0 * O + cb] = make_float2(v0, v1);
                *(float2*)&C[(size_t)r1 * O + cb] = make_float2(v2, v3);
            }
        }
    }
}

__global__ void __launch_bounds__(128) gemm_bf16_kernel(
    const __nv_bfloat16* __restrict__ A, const __nv_bfloat16* __restrict__ W,
    const float* __restrict__ R, float* __restrict__ C,
    __nv_bfloat16* __restrict__ Cb, float scale, int K, int O)
{
    gemm_bf16_body(A, W, R, C, Cb, scale, K, O);
}

// Batched QKV projection -> bf16 outputs; Q pre-scaled by 1/sqrt(dk).
__global__ void __launch_bounds__(128) gemm_qkv_kernel(
    const __nv_bfloat16* __restrict__ A,
    const __nv_bfloat16* __restrict__ Wq, const __nv_bfloat16* __restrict__ Wk,
    const __nv_bfloat16* __restrict__ Wv)
{
    const __nv_bfloat16* W = (blockIdx.z == 0) ? Wq : (blockIdx.z == 1) ? Wk : Wv;
    __nv_bfloat16* C = (blockIdx.z == 0) ? g_q : (blockIdx.z == 1) ? g_k : g_v;
    const float scale = (blockIdx.z == 0) ? 0.17677669529663687f : 1.f;
    gemm_bf16_body(A, W, nullptr, nullptr, C, scale, D_, D_);
}

// ============================================================================
// Flash attention, bf16 m16n8k16 mma. 2 row-blocks/warp (32 q rows/warp),
// CTA = 128 thr = 128 q rows. KV tiles of 64 keys, double-buffered cp.async.
// Output O written as bf16 (consumed by bf16 Wo GEMM).
// ============================================================================
#define AKVST 40   // K/V smem row stride in bf16 elements (80 bytes)
#define ATT_SMEM (2 * 2 * 64 * AKVST * 2)   // 20480 B

__global__ void __launch_bounds__(128, 3) attn_mma_kernel(
    const __nv_bfloat16* __restrict__ Q, const __nv_bfloat16* __restrict__ Kb,
    const __nv_bfloat16* __restrict__ Vb, __nv_bfloat16* __restrict__ Ob)
{
    extern __shared__ __align__(16) char dsm[];
    const unsigned ksb = smem_u32(dsm);                      // [2][64][AKVST] bf16
    const unsigned vsb = ksb + 2u * 64u * AKVST * 2u;        // [2][64][AKVST] bf16

    const int tid  = threadIdx.x;
    const int lane = tid & 31;
    const int warp = tid >> 5;
    const int g = lane >> 2;
    const int t = lane & 3;
    const int b = blockIdx.z, h = blockIdx.y;
    const int q0 = blockIdx.x * 128;
    const int r0 = warp * 32;

    // ---- Q fragments (bf16, pre-scaled by producer) ----
    unsigned qf[2][2][4];
#pragma unroll
    for (int rb = 0; rb < 2; rb++) {
        const __nv_bfloat16* q0p = Q + (size_t)(b * S_ + q0 + r0 + rb * 16 + g    ) * D_ + h * DK_;
        const __nv_bfloat16* q1p = Q + (size_t)(b * S_ + q0 + r0 + rb * 16 + g + 8) * D_ + h * DK_;
#pragma unroll
        for (int kt = 0; kt < 2; kt++) {
            qf[rb][kt][0] = *(const unsigned*)(q0p + kt * 16 + 2 * t);
            qf[rb][kt][1] = *(const unsigned*)(q1p + kt * 16 + 2 * t);
            qf[rb][kt][2] = *(const unsigned*)(q0p + kt * 16 + 2 * t + 8);
            qf[rb][kt][3] = *(const unsigned*)(q1p + kt * 16 + 2 * t + 8);
        }
    }

    // ---- KV tile loader ----
    const int krow = tid >> 1;
    const int ch0  = (tid & 1) * 2;

    {
        const __nv_bfloat16* kg = Kb + (size_t)(b * S_ + krow) * D_ + h * DK_;
        const __nv_bfloat16* vg = Vb + (size_t)(b * S_ + krow) * D_ + h * DK_;
#pragma unroll
        for (int i = 0; i < 2; i++) {
            int ch = ch0 + i;
            cp16(ksb + (unsigned)(krow * 80 + ch * 16), kg + ch * 8);
            cp16(vsb + (unsigned)(krow * 80 + ch * 16), vg + ch * 8);
        }
        asm volatile("cp.async.commit_group;" ::: "memory");
    }

    float m_[2][2], l_[2][2];
    float oa[2][4][4];
#pragma unroll
    for (int rb = 0; rb < 2; rb++) {
        m_[rb][0] = -1e30f; m_[rb][1] = -1e30f;
        l_[rb][0] = 0.f;    l_[rb][1] = 0.f;
#pragma unroll
        for (int ni = 0; ni < 4; ni++)
#pragma unroll
            for (int r = 0; r < 4; r++) oa[rb][ni][r] = 0.f;
    }

    const int ntiles = S_ / 64;
    const unsigned stage_b = 64u * 80u;

    const unsigned k_lrow = (unsigned)(lane & 7);
    const unsigned k_lcol = (unsigned)(lane >> 3) * 16u;
    const unsigned v_lrow = (unsigned)((lane & 7) + ((lane >> 3) & 1) * 8);
    const unsigned v_lcol = (unsigned)(lane >> 4) * 16u;

    for (int tile = 0; tile < ntiles; tile++) {
        const int s = tile & 1;
        const unsigned kst = ksb + (unsigned)s * stage_b;
        const unsigned vst = vsb + (unsigned)s * stage_b;

        if (tile + 1 < ntiles) {
            const int sn = s ^ 1;
            const __nv_bfloat16* kg = Kb + (size_t)(b * S_ + (tile + 1) * 64 + krow) * D_ + h * DK_;
            const __nv_bfloat16* vg = Vb + (size_t)(b * S_ + (tile + 1) * 64 + krow) * D_ + h * DK_;
#pragma unroll
            for (int i = 0; i < 2; i++) {
                int ch = ch0 + i;
                cp16(ksb + (unsigned)(sn * stage_b + krow * 80 + ch * 16), kg + ch * 8);
                cp16(vsb + (unsigned)(sn * stage_b + krow * 80 + ch * 16), vg + ch * 8);
            }
            asm volatile("cp.async.commit_group;" ::: "memory");
            asm volatile("cp.async.wait_group 1;" ::: "memory");
        } else {
            asm volatile("cp.async.wait_group 0;" ::: "memory");
        }
        __syncthreads();

        // ---- scores ----
        float sc[2][8][4];
#pragma unroll
        for (int rb = 0; rb < 2; rb++)
#pragma unroll
            for (int ni = 0; ni < 8; ni++)
#pragma unroll
                for (int r = 0; r < 4; r++) sc[rb][ni][r] = 0.f;

#pragma unroll
        for (int ni = 0; ni < 8; ni++) {
            unsigned kb[4];
            ldsm_x4(kb, kst + (unsigned)(ni * 8 + k_lrow) * 80u + k_lcol);
#pragma unroll
            for (int rb = 0; rb < 2; rb++) {
                mma_bf16(sc[rb][ni][0], sc[rb][ni][1], sc[rb][ni][2], sc[rb][ni][3],
                         qf[rb][0][0], qf[rb][0][1], qf[rb][0][2], qf[rb][0][3], kb[0], kb[1]);
                mma_bf16(sc[rb][ni][0], sc[rb][ni][1], sc[rb][ni][2], sc[rb][ni][3],
                         qf[rb][1][0], qf[rb][1][1], qf[rb][1][2], qf[rb][1][3], kb[2], kb[3]);
            }
        }

        // ---- online softmax ----
        float mn[2][2], e[2][2];
#pragma unroll
        for (int rb = 0; rb < 2; rb++) {
            float mx0 = -1e30f, mx1 = -1e30f;
#pragma unroll
            for (int ni = 0; ni < 8; ni++) {
                mx0 = fmaxf(mx0, fmaxf(sc[rb][ni][0], sc[rb][ni][1]));
                mx1 = fmaxf(mx1, fmaxf(sc[rb][ni][2], sc[rb][ni][3]));
            }
            mx0 = fmaxf(mx0, __shfl_xor_sync(0xffffffffu, mx0, 1));
            mx0 = fmaxf(mx0, __shfl_xor_sync(0xffffffffu, mx0, 2));
            mx1 = fmaxf(mx1, __shfl_xor_sync(0xffffffffu, mx1, 1));
            mx1 = fmaxf(mx1, __shfl_xor_sync(0xffffffffu, mx1, 2));
            mn[rb][0] = fmaxf(m_[rb][0], mx0);
            mn[rb][1] = fmaxf(m_[rb][1], mx1);
            e[rb][0] = __expf(m_[rb][0] - mn[rb][0]);
            e[rb][1] = __expf(m_[rb][1] - mn[rb][1]);
            m_[rb][0] = mn[rb][0]; m_[rb][1] = mn[rb][1];
#pragma unroll
            for (int ni = 0; ni < 4; ni++) {
                oa[rb][ni][0] *= e[rb][0]; oa[rb][ni][1] *= e[rb][0];
                oa[rb][ni][2] *= e[rb][1]; oa[rb][ni][3] *= e[rb][1];
            }
        }

        // ---- PV ----
        float rs[2][2] = {{0.f, 0.f}, {0.f, 0.f}};

#pragma unroll
        for (int kk = 0; kk < 4; kk++) {
            unsigned v0[4], v1[4];
            const unsigned vrow = vst + (unsigned)(kk * 16 + v_lrow) * 80u + v_lcol;
            ldsm_x4_t(v0, vrow);
            ldsm_x4_t(v1, vrow + 32u);
#pragma unroll
            for (int rb = 0; rb < 2; rb++) {
                float e00 = __expf(sc[rb][2*kk  ][0] - mn[rb][0]);
                float e01 = __expf(sc[rb][2*kk  ][1] - mn[rb][0]);
                float e02 = __expf(sc[rb][2*kk  ][2] - mn[rb][1]);
                float e03 = __expf(sc[rb][2*kk  ][3] - mn[rb][1]);
                float f00 = __expf(sc[rb][2*kk+1][0] - mn[rb][0]);
                float f01 = __expf(sc[rb][2*kk+1][1] - mn[rb][0]);
                float f02 = __expf(sc[rb][2*kk+1][2] - mn[rb][1]);
                float f03 = __expf(sc[rb][2*kk+1][3] - mn[rb][1]);
                rs[rb][0] += e00 + e01 + f00 + f01;
                rs[rb][1] += e02 + e03 + f02 + f03;

                unsigned a0 = pack_bf16(e00, e01);
                unsigned a1 = pack_bf16(e02, e03);
                unsigned a2 = pack_bf16(f00, f01);
                unsigned a3 = pack_bf16(f02, f03);

                mma_bf16(oa[rb][0][0], oa[rb][0][1], oa[rb][0][2], oa[rb][0][3],
                         a0, a1, a2, a3, v0[0], v0[1]);
                mma_bf16(oa[rb][1][0], oa[rb][1][1], oa[rb][1][2], oa[rb][1][3],
                         a0, a1, a2, a3, v0[2], v0[3]);
                mma_bf16(oa[rb][2][0], oa[rb][2][1], oa[rb][2][2], oa[rb][2][3],
                         a0, a1, a2, a3, v1[0], v1[1]);
                mma_bf16(oa[rb][3][0], oa[rb][3][1], oa[rb][3][2], oa[rb][3][3],
                         a0, a1, a2, a3, v1[2], v1[3]);
            }
        }

#pragma unroll
        for (int rb = 0; rb < 2; rb++) {
            float r0s = rs[rb][0], r1s = rs[rb][1];
            r0s += __shfl_xor_sync(0xffffffffu, r0s, 1);
            r0s += __shfl_xor_sync(0xffffffffu, r0s, 2);
            r1s += __shfl_xor_sync(0xffffffffu, r1s, 1);
            r1s += __shfl_xor_sync(0xffffffffu, r1s, 2);
            l_[rb][0] = l_[rb][0] * e[rb][0] + r0s;
            l_[rb][1] = l_[rb][1] * e[rb][1] + r1s;
        }

        __syncthreads();
    }

    // ---- write O = acc / l (bf16) ----
#pragma unroll
    for (int rb = 0; rb < 2; rb++) {
        const float inv0 = 1.f / l_[rb][0];
        const float inv1 = 1.f / l_[rb][1];
#pragma unroll
        for (int ni = 0; ni < 4; ni++) {
            const int cb = h * DK_ + ni * 8 + 2 * t;
            size_t ra = (size_t)(b * S_ + q0 + r0 + rb * 16 + g    ) * D_ + cb;
            size_t rx = (size_t)(b * S_ + q0 + r0 + rb * 16 + g + 8) * D_ + cb;
            *(unsigned*)&Ob[ra] = pack_bf16(oa[rb][ni][0] * inv0, oa[rb][ni][1] * inv0);
            *(unsigned*)&Ob[rx] = pack_bf16(oa[rb][ni][2] * inv1, oa[rb][ni][3] * inv1);
        }
    }
}

// ============================================================================
// LayerNorm over last dim (256). One-pass. Dual write: fp32 stream + bf16 feed.
// ============================================================================
__global__ void __launch_bounds__(256) ln_kernel(
    const float* __restrict__ X, const float* __restrict__ g,
    const float* __restrict__ b, float* __restrict__ Y,
    __nv_bfloat16* __restrict__ Yb)
{
    __shared__ float red[8], red2[8];
    const int row = blockIdx.x;
    const int tid = threadIdx.x;
    const int lane = tid & 31, warp = tid >> 5;

    float v = X[(size_t)row * D_ + tid];
    float s  = warp_sum(v);
    float s2 = warp_sum(v * v);
    if (!lane) { red[warp] = s; red2[warp] = s2; }
    __syncthreads();
    if (tid < 32) {
        float a = (tid < 8) ? red[tid]  : 0.f;
        float c = (tid < 8) ? red2[tid] : 0.f;
        a = warp_sum(a);
        c = warp_sum(c);
        if (!tid) { red[0] = a; red2[0] = c; }
    }
    __syncthreads();
    float mu  = red[0]  * (1.f / D_);
    float var = red2[0] * (1.f / D_) - mu * mu;
    float y = (v - mu) * rsqrtf(var + LNEPS) * g[tid] + b[tid];
    Y[(size_t)row * D_ + tid] = y;
    if (Yb) Yb[(size_t)row * D_ + tid] = __float2bfloat16(y);
}

// ============================================================================
// host
// ============================================================================
extern "C" void kernel_launch(void* const* d_in, const int* in_sizes, int n_in,
                              void* d_out, int out_size)
{
    const float* x    = (const float*)d_in[0];
    const float* W11  = (const float*)d_in[1];
    const float* W12  = (const float*)d_in[2];
    const float* W13  = (const float*)d_in[3];
    const float* W14  = (const float*)d_in[4];
    const float* W21  = (const float*)d_in[5];
    const float* W22  = (const float*)d_in[6];
    const float* W23  = (const float*)d_in[7];
    const float* W24  = (const float*)d_in[8];
    const float* Wf11 = (const float*)d_in[9];
    const float* Wf21 = (const float*)d_in[10];
    const float* Wf12 = (const float*)d_in[11];
    const float* Wf22 = (const float*)d_in[12];
    const float* g1   = (const float*)d_in[13];
    const float* b1   = (const float*)d_in[14];
    const float* g2   = (const float*)d_in[15];
    const float* b2   = (const float*)d_in[16];
    const float* g3   = (const float*)d_in[17];
    const float* b3   = (const float*)d_in[18];
    const float* g4   = (const float*)d_in[19];
    const float* b4   = (const float*)d_in[20];
    float* out = (float*)d_out;

    __nv_bfloat16 *q, *k, *v, *o, *xb, *x2b, *hbuf, *wb;
    float *x1, *x2;
    cudaGetSymbolAddress((void**)&q,    g_q);
    cudaGetSymbolAddress((void**)&k,    g_k);
    cudaGetSymbolAddress((void**)&v,    g_v);
    cudaGetSymbolAddress((void**)&o,    g_o);
    cudaGetSymbolAddress((void**)&xb,   g_xb);
    cudaGetSymbolAddress((void**)&x2b,  g_x2b);
    cudaGetSymbolAddress((void**)&hbuf, g_h);
    cudaGetSymbolAddress((void**)&wb,   g_wb);
    cudaGetSymbolAddress((void**)&x1,   g_x1);
    cudaGetSymbolAddress((void**)&x2,   g_x2);

    cudaFuncSetAttribute(attn_mma_kernel,
                         cudaFuncAttributeMaxDynamicSharedMemorySize, ATT_SMEM);

    dim3 agrid(S_ / 128, H_, B_);
    dim3 qkvgrid(D_ / 128, M_ / 64, 3);
    dim3 ggridD(D_ / 128, M_ / 64);
    dim3 ggridF(DFF_ / 128, M_ / 64);

    convert_kernel<<<7168, 256>>>(x, W11, W12, W13, W14, W21, W22, W23, W24,
                                  Wf11, Wf21, Wf12, Wf22);

    // ---------------- block 1 ----------------
    gemm_qkv_kernel<<<qkvgrid, 128>>>(xb, wb + WOFF_11, wb + WOFF_12, wb + WOFF_13);
    attn_mma_kernel<<<agrid, 128, ATT_SMEM>>>(q, k, v, o);
    gemm_bf16_kernel<<<ggridD, 128>>>(o, wb + WOFF_14, x, x1, nullptr, 1.f, D_, D_);
    ln_kernel<<<M_, 256>>>(x1, g1, b1, x2, x2b);
    gemm_bf16_kernel<<<ggridF, 128>>>(x2b, wb + WOFF_F11, nullptr, nullptr, hbuf, 1.f, D_, DFF_);
    gemm_bf16_kernel<<<ggridD, 128>>>(hbuf, wb + WOFF_F21, x2, x1, nullptr, 1.f, DFF_, D_);
    ln_kernel<<<M_, 256>>>(x1, g2, b2, x2, x2b);

    // ---------------- block 2 ----------------
    gemm_qkv_kernel<<<qkvgrid, 128>>>(x2b, wb + WOFF_21, wb + WOFF_22, wb + WOFF_23);
    attn_mma_kernel<<<agrid, 128, ATT_SMEM>>>(q, k, v, o);
    gemm_bf16_kernel<<<ggridD, 128>>>(o, wb + WOFF_24, x2, x1, nullptr, 1.f, D_, D_);
    ln_kernel<<<M_, 256>>>(x1, g3, b3, x2, x2b);
    gemm_bf16_kernel<<<ggridF, 128>>>(x2b, wb + WOFF_F12, nullptr, nullptr, hbuf, 1.f, D_, DFF_);
    gemm_bf16_kernel<<<ggridD, 128>>>(hbuf, wb + WOFF_F22, x2, x1, nullptr, 1.f, DFF_, D_);
    ln_kernel<<<M_, 256>>>(x1, g4, b4, out, nullptr);
}